// round 1
// baseline (speedup 1.0000x reference)
#include <cuda_runtime.h>
#include <math.h>

#define Nn 50000
#define Ee 400000
#define INDIM 256
#define EDGEF 64
#define OUTD 32
#define EOUT 64
#define Hh 8
#define HD 256           // Hh*OUTD
#define ALPHA 0.2f
#define EPSB 1e-5f

// ---------------- scratch (static device globals; no allocation) ----------------
__device__ float g_ft[Nn * HD];          // node projection [N,H,D]
__device__ float g_a1[Nn * Hh];
__device__ float g_a2[Nn * Hh];
__device__ float g_apre[Ee * Hh];        // pre-softmax attention logits
__device__ float g_amax[Nn * Hh];        // segment max
__device__ float g_z[Nn * Hh];           // segment sum of exp
__device__ float g_agg[Nn * HD];         // aggregated messages
__device__ double g_nsum[HD], g_nsumsq[HD];
__device__ double g_esum[EOUT], g_esumsq[EOUT];

__device__ __forceinline__ float lrelu(float x) { return x > 0.f ? x : ALPHA * x; }

__device__ __forceinline__ void atomicMaxFloat(float* addr, float val) {
    if (val >= 0.f) atomicMax((int*)addr, __float_as_int(val));
    else            atomicMin((unsigned int*)addr, __float_as_uint(val));
}

// ---------------- init: zero / -inf all accumulators ----------------
__global__ void k_init() {
    int stride = gridDim.x * blockDim.x;
    for (int i = blockIdx.x * blockDim.x + threadIdx.x; i < Nn * HD; i += stride) {
        g_agg[i] = 0.f;
        if (i < Nn * Hh) { g_z[i] = 0.f; g_amax[i] = -INFINITY; }
        if (i < HD)      { g_nsum[i] = 0.0; g_nsumsq[i] = 0.0; }
        if (i < EOUT)    { g_esum[i] = 0.0; g_esumsq[i] = 0.0; }
    }
}

// ---------------- ft = node_inputs @ fc_w  (M=50000, N=256, K=256) ----------------
#define GTM 64
#define GTN 64
#define GTK 16
#define GPAD 68
__global__ void k_gemm_ft(const float* __restrict__ A, const float* __restrict__ B) {
    __shared__ float As[GTK][GPAD];
    __shared__ float Bs[GTK][GPAD];
    int tid = threadIdx.x;                      // 256
    int bm = blockIdx.y * GTM, bn = blockIdx.x * GTN;
    int tm = (tid >> 4) << 2, tn = (tid & 15) << 2;
    float acc[4][4] = {};
    for (int k0 = 0; k0 < INDIM; k0 += GTK) {
        #pragma unroll
        for (int j = 0; j < 4; j++) {
            int e = tid + j * 256;
            int m = e >> 4, k = e & 15;
            int gm = bm + m;
            As[k][m] = (gm < Nn) ? A[gm * INDIM + k0 + k] : 0.f;
        }
        #pragma unroll
        for (int j = 0; j < 4; j++) {
            int e = tid + j * 256;
            int kk = e >> 6, n = e & 63;
            Bs[kk][n] = B[(k0 + kk) * HD + bn + n];
        }
        __syncthreads();
        #pragma unroll
        for (int k = 0; k < GTK; k++) {
            float4 a4 = *(const float4*)&As[k][tm];
            float4 b4 = *(const float4*)&Bs[k][tn];
            float a[4] = {a4.x, a4.y, a4.z, a4.w};
            float b[4] = {b4.x, b4.y, b4.z, b4.w};
            #pragma unroll
            for (int i = 0; i < 4; i++)
                #pragma unroll
                for (int j = 0; j < 4; j++)
                    acc[i][j] += a[i] * b[j];
        }
        __syncthreads();
    }
    #pragma unroll
    for (int i = 0; i < 4; i++) {
        int gm = bm + tm + i;
        if (gm < Nn) {
            #pragma unroll
            for (int j = 0; j < 4; j++)
                g_ft[gm * HD + bn + tn + j] = acc[i][j];
        }
    }
}

// ---------------- per-node, per-head attention scalars ----------------
__global__ void k_attn(const float* __restrict__ attn_l, const float* __restrict__ attn_r) {
    int gw = (blockIdx.x * blockDim.x + threadIdx.x) >> 5;
    int lane = threadIdx.x & 31;
    if (gw >= Nn) return;
    #pragma unroll
    for (int h = 0; h < Hh; h++) {
        float v = g_ft[gw * HD + h * OUTD + lane];
        float s1 = v * attn_l[h * OUTD + lane];
        float s2 = v * attn_r[h * OUTD + lane];
        #pragma unroll
        for (int o = 16; o; o >>= 1) {
            s1 += __shfl_down_sync(0xffffffffu, s1, o);
            s2 += __shfl_down_sync(0xffffffffu, s2, o);
        }
        if (lane == 0) { g_a1[gw * Hh + h] = s1; g_a2[gw * Hh + h] = s2; }
    }
}

// ---------------- edge attention MLP + logits + segment max ----------------
__global__ void k_edge_attn(const float* __restrict__ ein,
                            const float* __restrict__ w1, const float* __restrict__ b1,
                            const float* __restrict__ w2, const float* __restrict__ b2,
                            const int* __restrict__ src, const int* __restrict__ dst) {
    __shared__ float sx[128 * 65];
    __shared__ float sw1[EDGEF * OUTD];
    __shared__ float sw2[OUTD * Hh];
    __shared__ float sb1[OUTD];
    __shared__ float sb2[Hh];
    int tid = threadIdx.x;                      // 128
    int e0 = blockIdx.x * 128;
    for (int i = tid; i < EDGEF * OUTD; i += 128) sw1[i] = w1[i];
    for (int i = tid; i < OUTD * Hh; i += 128) sw2[i] = w2[i];
    if (tid < OUTD) sb1[tid] = b1[tid];
    if (tid < Hh)   sb2[tid] = b2[tid];
    for (int i = tid; i < 128 * EDGEF; i += 128) {
        int r = i >> 6, c = i & 63;
        int e = e0 + r;
        sx[r * 65 + c] = (e < Ee) ? ein[e * EDGEF + c] : 0.f;
    }
    __syncthreads();
    int e = e0 + tid;
    if (e >= Ee) return;
    const float* x = &sx[tid * 65];
    float acc[Hh];
    #pragma unroll
    for (int h = 0; h < Hh; h++) acc[h] = sb2[h];
    for (int i = 0; i < OUTD; i++) {
        float s = sb1[i];
        #pragma unroll
        for (int k = 0; k < EDGEF; k++) s += x[k] * sw1[k * OUTD + i];
        s = lrelu(s);
        #pragma unroll
        for (int h = 0; h < Hh; h++) acc[h] += s * sw2[i * Hh + h];
    }
    int sn = src[e], dn = dst[e];
    #pragma unroll
    for (int h = 0; h < Hh; h++) {
        float a = lrelu(acc[h] + g_a1[sn * Hh + h] + g_a2[dn * Hh + h]);   // TEMP = 1
        g_apre[e * Hh + h] = a;
        atomicMaxFloat(&g_amax[dn * Hh + h], a);
    }
}

// ---------------- exp, z-sum, weighted aggregation (warp per edge) ----------------
__global__ void k_aggregate(const int* __restrict__ src, const int* __restrict__ dst) {
    int gw = (blockIdx.x * blockDim.x + threadIdx.x) >> 5;
    int lane = threadIdx.x & 31;
    if (gw >= Ee) return;
    int sn = src[gw], dn = dst[gw];
    float aexp = 0.f;
    if (lane < Hh) {
        float a = g_apre[gw * Hh + lane];
        float am = g_amax[dn * Hh + lane];
        aexp = expf(a - am);
        atomicAdd(&g_z[dn * Hh + lane], aexp);
    }
    #pragma unroll
    for (int h = 0; h < Hh; h++) {
        float w = __shfl_sync(0xffffffffu, aexp, h);
        float v = g_ft[sn * HD + h * OUTD + lane] * w;
        atomicAdd(&g_agg[dn * HD + h * OUTD + lane], v);
    }
}

// ---------------- node: agg/z + residual + lrelu, accumulate BN stats ----------------
__global__ void k_node_post(const float* __restrict__ nin, float* __restrict__ ynode) {
    int c = threadIdx.x;                        // 256 (= column)
    float s = 0.f, s2 = 0.f;
    for (int n = blockIdx.x; n < Nn; n += gridDim.x) {
        float zz = g_z[n * Hh + (c >> 5)];
        if (zz == 0.f) zz = 1.f;
        float v = g_agg[n * HD + c] / zz + nin[n * HD + c];
        v = lrelu(v);
        ynode[n * HD + c] = v;
        s += v; s2 += v * v;
    }
    atomicAdd(&g_nsum[c], (double)s);
    atomicAdd(&g_nsumsq[c], (double)s2);
}

__global__ void k_node_bn(float* __restrict__ ynode,
                          const float* __restrict__ g, const float* __restrict__ b) {
    int stride = gridDim.x * blockDim.x;
    for (int i = blockIdx.x * blockDim.x + threadIdx.x; i < Nn * HD; i += stride) {
        int c = i & 255;
        float mu = (float)(g_nsum[c] / (double)Nn);
        float var = (float)(g_nsumsq[c] / (double)Nn) - mu * mu;
        float sc = rsqrtf(var + EPSB) * g[c];
        ynode[i] = (ynode[i] - mu) * sc + b[c];
    }
}

// ---------------- edge update MLP (warp per edge, weights in smem) ----------------
#define EU_THREADS 512
#define EU_WARPS 16
#define EU_SMEM_FLOATS (512*64 + 64*64 + 128*64 + EU_WARPS*512)
__global__ void __launch_bounds__(EU_THREADS, 1)
k_edge_update(const float* __restrict__ ynode, const float* __restrict__ ein,
              const float* __restrict__ Wng, const float* __restrict__ W2g,
              const float* __restrict__ W3g,
              const int* __restrict__ src, const int* __restrict__ dst,
              float* __restrict__ yedge) {
    extern __shared__ float sm[];
    float* Wn = sm;                 // 512*64
    float* W2 = Wn + 512 * 64;      // 64*64
    float* W3 = W2 + 64 * 64;       // 128*64
    float* xb = W3 + 128 * 64;      // EU_WARPS * 512
    int tid = threadIdx.x;
    for (int i = tid; i < 512 * 64; i += EU_THREADS) Wn[i] = Wng[i];
    for (int i = tid; i < 64 * 64;  i += EU_THREADS) W2[i] = W2g[i];
    for (int i = tid; i < 128 * 64; i += EU_THREADS) W3[i] = W3g[i];
    __syncthreads();
    int wid = tid >> 5, lane = tid & 31;
    float* xw = xb + wid * 512;
    int nwarps = gridDim.x * EU_WARPS;
    int gw0 = blockIdx.x * EU_WARPS + wid;

    double s0 = 0, s1 = 0, q0 = 0, q1 = 0;

    for (int e = gw0; e < Ee; e += nwarps) {
        int sn = src[e], dn = dst[e];
        #pragma unroll
        for (int j = 0; j < 8; j++) {
            xw[j * 32 + lane]       = ynode[sn * HD + j * 32 + lane];
            xw[256 + j * 32 + lane] = ynode[dn * HD + j * 32 + lane];
        }
        __syncwarp();
        float nf0 = 0.f, nf1 = 0.f;
        #pragma unroll 8
        for (int k = 0; k < 512; k++) {
            float xv = xw[k];
            float2 w = *(const float2*)&Wn[k * 64 + 2 * lane];
            nf0 += xv * w.x; nf1 += xv * w.y;
        }
        __syncwarp();
        nf0 = lrelu(nf0); nf1 = lrelu(nf1);

        float e0r = ein[e * EDGEF + lane];
        float e1r = ein[e * EDGEF + 32 + lane];
        float ef0 = 0.f, ef1 = 0.f;
        #pragma unroll
        for (int k = 0; k < 64; k++) {
            float xv = __shfl_sync(0xffffffffu, (k < 32) ? e0r : e1r, k & 31);
            float2 w = *(const float2*)&W2[k * 64 + 2 * lane];
            ef0 += xv * w.x; ef1 += xv * w.y;
        }
        ef0 = lrelu(ef0); ef1 = lrelu(ef1);

        float2 res = *(const float2*)&ein[e * EDGEF + 2 * lane];
        float o0 = res.x, o1 = res.y;
        #pragma unroll
        for (int k = 0; k < 128; k++) {
            float cv;
            if (k < 64) cv = __shfl_sync(0xffffffffu, (k & 1) ? nf1 : nf0, k >> 1);
            else        cv = __shfl_sync(0xffffffffu, (k & 1) ? ef1 : ef0, (k - 64) >> 1);
            float2 w = *(const float2*)&W3[k * 64 + 2 * lane];
            o0 += cv * w.x; o1 += cv * w.y;
        }
        o0 = lrelu(o0); o1 = lrelu(o1);
        float2 outv; outv.x = o0; outv.y = o1;
        *(float2*)&yedge[e * EOUT + 2 * lane] = outv;
        s0 += (double)o0; s1 += (double)o1;
        q0 += (double)(o0 * o0); q1 += (double)(o1 * o1);
    }

    // block-level reduction of BN partial sums, then atomics
    __syncthreads();
    double* red = (double*)xb;      // 16 KB needed, 32 KB available
    red[wid * 128 + lane * 4 + 0] = s0;
    red[wid * 128 + lane * 4 + 1] = s1;
    red[wid * 128 + lane * 4 + 2] = q0;
    red[wid * 128 + lane * 4 + 3] = q1;
    __syncthreads();
    if (tid < 128) {
        double t = 0;
        #pragma unroll
        for (int w = 0; w < EU_WARPS; w++) t += red[w * 128 + tid];
        int l = tid >> 2, part = tid & 3;
        if (part == 0) atomicAdd(&g_esum[2 * l], t);
        else if (part == 1) atomicAdd(&g_esum[2 * l + 1], t);
        else if (part == 2) atomicAdd(&g_esumsq[2 * l], t);
        else atomicAdd(&g_esumsq[2 * l + 1], t);
    }
}

__global__ void k_edge_bn(float* __restrict__ yedge,
                          const float* __restrict__ g, const float* __restrict__ b) {
    int stride = gridDim.x * blockDim.x;
    for (long long i = blockIdx.x * blockDim.x + threadIdx.x; i < (long long)Ee * EOUT; i += stride) {
        int c = (int)(i & 63);
        float mu = (float)(g_esum[c] / (double)Ee);
        float var = (float)(g_esumsq[c] / (double)Ee) - mu * mu;
        float sc = rsqrtf(var + EPSB) * g[c];
        yedge[i] = (yedge[i] - mu) * sc + b[c];
    }
}

// ---------------- launch ----------------
extern "C" void kernel_launch(void* const* d_in, const int* in_sizes, int n_in,
                              void* d_out, int out_size) {
    const float* node_inputs = (const float*)d_in[0];
    const float* edge_inputs = (const float*)d_in[1];
    const float* fc_w        = (const float*)d_in[2];
    const float* attn_l      = (const float*)d_in[3];
    const float* attn_r      = (const float*)d_in[4];
    const float* ae_w1       = (const float*)d_in[5];
    const float* ae_b1       = (const float*)d_in[6];
    const float* ae_w2       = (const float*)d_in[7];
    const float* ae_b2       = (const float*)d_in[8];
    const float* bn_n_g      = (const float*)d_in[9];
    const float* bn_n_b      = (const float*)d_in[10];
    const float* eu_node_w   = (const float*)d_in[11];
    const float* eu_edge_w   = (const float*)d_in[12];
    const float* eu_final_w  = (const float*)d_in[13];
    const float* bn_e_g      = (const float*)d_in[14];
    const float* bn_e_b      = (const float*)d_in[15];
    const int*   src         = (const int*)d_in[16];
    const int*   dst         = (const int*)d_in[17];

    float* out_node = (float*)d_out;
    float* out_edge = out_node + (size_t)Nn * HD;

    k_init<<<4096, 256>>>();

    dim3 ggrid(HD / GTN, (Nn + GTM - 1) / GTM);
    k_gemm_ft<<<ggrid, 256>>>(node_inputs, fc_w);

    k_attn<<<(Nn * 32 + 255) / 256, 256>>>(attn_l, attn_r);

    k_edge_attn<<<(Ee + 127) / 128, 128>>>(edge_inputs, ae_w1, ae_b1, ae_w2, ae_b2, src, dst);

    k_aggregate<<<(Ee * 32 + 255) / 256, 256>>>(src, dst);

    k_node_post<<<512, 256>>>(node_inputs, out_node);
    k_node_bn<<<8192, 256>>>(out_node, bn_n_g, bn_n_b);

    static_assert(EU_SMEM_FLOATS * 4 <= 232448, "smem");
    cudaFuncSetAttribute(k_edge_update, cudaFuncAttributeMaxDynamicSharedMemorySize,
                         EU_SMEM_FLOATS * 4);
    k_edge_update<<<296, EU_THREADS, EU_SMEM_FLOATS * 4>>>(
        out_node, edge_inputs, eu_node_w, eu_edge_w, eu_final_w, src, dst, out_edge);

    k_edge_bn<<<8192, 256>>>(out_edge, bn_e_g, bn_e_b);
}

// round 2
// speedup vs baseline: 1.6653x; 1.6653x over previous
#include <cuda_runtime.h>
#include <math.h>

#define Nn 50000
#define Ee 400000
#define INDIM 256
#define EDGEF 64
#define OUTD 32
#define EOUT 64
#define Hh 8
#define HD 256           // Hh*OUTD
#define ALPHA 0.2f
#define EPSB 1e-5f

// ---------------- scratch (static device globals; no allocation) ----------------
__device__ float g_ft[Nn * HD];          // node projection [N,H,D]
__device__ float g_a1[Nn * Hh];
__device__ float g_a2[Nn * Hh];
__device__ float g_apre[Ee * Hh];        // pre-softmax attention logits
__device__ float g_amax[Nn * Hh];        // segment max
__device__ float g_z[Nn * Hh];           // segment sum of exp
__device__ float g_agg[Nn * HD];         // aggregated messages
__device__ float g_pq[Nn * 128];         // P (cols 0..63) | Q (cols 64..127)
__device__ double g_nsum[HD], g_nsumsq[HD];
__device__ double g_esum[EOUT], g_esumsq[EOUT];

__device__ __forceinline__ float lrelu(float x) { return x > 0.f ? x : ALPHA * x; }

__device__ __forceinline__ void atomicMaxFloat(float* addr, float val) {
    if (val >= 0.f) atomicMax((int*)addr, __float_as_int(val));
    else            atomicMin((unsigned int*)addr, __float_as_uint(val));
}

__device__ __forceinline__ void red_add_v4(float* addr, float4 v) {
    asm volatile("red.global.add.v4.f32 [%0], {%1,%2,%3,%4};"
                 :: "l"(addr), "f"(v.x), "f"(v.y), "f"(v.z), "f"(v.w) : "memory");
}

// ---------------- init: zero / -inf all accumulators ----------------
__global__ void k_init() {
    int stride = gridDim.x * blockDim.x;
    for (int i = blockIdx.x * blockDim.x + threadIdx.x; i < Nn * HD; i += stride) {
        g_agg[i] = 0.f;
        if (i < Nn * Hh) { g_z[i] = 0.f; g_amax[i] = -INFINITY; }
        if (i < HD)      { g_nsum[i] = 0.0; g_nsumsq[i] = 0.0; }
        if (i < EOUT)    { g_esum[i] = 0.0; g_esumsq[i] = 0.0; }
    }
}

// ---------------- ft = node_inputs @ fc_w  (M=50000, N=256, K=256) ----------------
#define GTM 64
#define GTN 64
#define GTK 16
#define GPAD 68
__global__ void k_gemm_ft(const float* __restrict__ A, const float* __restrict__ B) {
    __shared__ float As[GTK][GPAD];
    __shared__ float Bs[GTK][GPAD];
    int tid = threadIdx.x;                      // 256
    int bm = blockIdx.y * GTM, bn = blockIdx.x * GTN;
    int tm = (tid >> 4) << 2, tn = (tid & 15) << 2;
    float acc[4][4] = {};
    for (int k0 = 0; k0 < INDIM; k0 += GTK) {
        #pragma unroll
        for (int j = 0; j < 4; j++) {
            int e = tid + j * 256;
            int m = e >> 4, k = e & 15;
            int gm = bm + m;
            As[k][m] = (gm < Nn) ? A[gm * INDIM + k0 + k] : 0.f;
        }
        #pragma unroll
        for (int j = 0; j < 4; j++) {
            int e = tid + j * 256;
            int kk = e >> 6, n = e & 63;
            Bs[kk][n] = B[(k0 + kk) * HD + bn + n];
        }
        __syncthreads();
        #pragma unroll
        for (int k = 0; k < GTK; k++) {
            float4 a4 = *(const float4*)&As[k][tm];
            float4 b4 = *(const float4*)&Bs[k][tn];
            float a[4] = {a4.x, a4.y, a4.z, a4.w};
            float b[4] = {b4.x, b4.y, b4.z, b4.w};
            #pragma unroll
            for (int i = 0; i < 4; i++)
                #pragma unroll
                for (int j = 0; j < 4; j++)
                    acc[i][j] += a[i] * b[j];
        }
        __syncthreads();
    }
    #pragma unroll
    for (int i = 0; i < 4; i++) {
        int gm = bm + tm + i;
        if (gm < Nn) {
            #pragma unroll
            for (int j = 0; j < 4; j++)
                g_ft[gm * HD + bn + tn + j] = acc[i][j];
        }
    }
}

// ---------------- g_pq = ynode @ [Wn_top | Wn_bot]  (M=50000, N=128, K=256) ------
__global__ void k_pq_gemm(const float* __restrict__ A, const float* __restrict__ Wn) {
    __shared__ float As[GTK][GPAD];
    __shared__ float Bs[GTK][GPAD];
    int tid = threadIdx.x;                      // 256
    int bm = blockIdx.y * GTM, bn = blockIdx.x * GTN;   // bn in {0, 64}
    int tm = (tid >> 4) << 2, tn = (tid & 15) << 2;
    float acc[4][4] = {};
    for (int k0 = 0; k0 < INDIM; k0 += GTK) {
        #pragma unroll
        for (int j = 0; j < 4; j++) {
            int e = tid + j * 256;
            int m = e >> 4, k = e & 15;
            int gm = bm + m;
            As[k][m] = (gm < Nn) ? A[gm * HD + k0 + k] : 0.f;
        }
        #pragma unroll
        for (int j = 0; j < 4; j++) {
            int e = tid + j * 256;
            int kk = e >> 6, n = e & 63;
            int jg = bn + n;                    // global output col 0..127
            int row = (jg < 64) ? (k0 + kk) : (256 + k0 + kk);
            Bs[kk][n] = Wn[row * 64 + (jg & 63)];
        }
        __syncthreads();
        #pragma unroll
        for (int k = 0; k < GTK; k++) {
            float4 a4 = *(const float4*)&As[k][tm];
            float4 b4 = *(const float4*)&Bs[k][tn];
            float a[4] = {a4.x, a4.y, a4.z, a4.w};
            float b[4] = {b4.x, b4.y, b4.z, b4.w};
            #pragma unroll
            for (int i = 0; i < 4; i++)
                #pragma unroll
                for (int j = 0; j < 4; j++)
                    acc[i][j] += a[i] * b[j];
        }
        __syncthreads();
    }
    #pragma unroll
    for (int i = 0; i < 4; i++) {
        int gm = bm + tm + i;
        if (gm < Nn) {
            #pragma unroll
            for (int j = 0; j < 4; j++)
                g_pq[gm * 128 + bn + tn + j] = acc[i][j];
        }
    }
}

// ---------------- per-node, per-head attention scalars ----------------
__global__ void k_attn(const float* __restrict__ attn_l, const float* __restrict__ attn_r) {
    int gw = (blockIdx.x * blockDim.x + threadIdx.x) >> 5;
    int lane = threadIdx.x & 31;
    if (gw >= Nn) return;
    #pragma unroll
    for (int h = 0; h < Hh; h++) {
        float v = g_ft[gw * HD + h * OUTD + lane];
        float s1 = v * attn_l[h * OUTD + lane];
        float s2 = v * attn_r[h * OUTD + lane];
        #pragma unroll
        for (int o = 16; o; o >>= 1) {
            s1 += __shfl_down_sync(0xffffffffu, s1, o);
            s2 += __shfl_down_sync(0xffffffffu, s2, o);
        }
        if (lane == 0) { g_a1[gw * Hh + h] = s1; g_a2[gw * Hh + h] = s2; }
    }
}

// ---------------- edge attention MLP + logits + segment max ----------------
__global__ void k_edge_attn(const float* __restrict__ ein,
                            const float* __restrict__ w1, const float* __restrict__ b1,
                            const float* __restrict__ w2, const float* __restrict__ b2,
                            const int* __restrict__ src, const int* __restrict__ dst) {
    __shared__ float sx[128 * 65];
    __shared__ float sw1[EDGEF * OUTD];
    __shared__ float sw2[OUTD * Hh];
    __shared__ float sb1[OUTD];
    __shared__ float sb2[Hh];
    int tid = threadIdx.x;                      // 128
    int e0 = blockIdx.x * 128;
    for (int i = tid; i < EDGEF * OUTD; i += 128) sw1[i] = w1[i];
    for (int i = tid; i < OUTD * Hh; i += 128) sw2[i] = w2[i];
    if (tid < OUTD) sb1[tid] = b1[tid];
    if (tid < Hh)   sb2[tid] = b2[tid];
    for (int i = tid; i < 128 * EDGEF; i += 128) {
        int r = i >> 6, c = i & 63;
        int e = e0 + r;
        sx[r * 65 + c] = (e < Ee) ? ein[e * EDGEF + c] : 0.f;
    }
    __syncthreads();
    int e = e0 + tid;
    if (e >= Ee) return;
    const float* x = &sx[tid * 65];
    float acc[Hh];
    #pragma unroll
    for (int h = 0; h < Hh; h++) acc[h] = sb2[h];
    for (int i = 0; i < OUTD; i++) {
        float s = sb1[i];
        #pragma unroll
        for (int k = 0; k < EDGEF; k++) s += x[k] * sw1[k * OUTD + i];
        s = lrelu(s);
        #pragma unroll
        for (int h = 0; h < Hh; h++) acc[h] += s * sw2[i * Hh + h];
    }
    int sn = src[e], dn = dst[e];
    #pragma unroll
    for (int h = 0; h < Hh; h++) {
        float a = lrelu(acc[h] + g_a1[sn * Hh + h] + g_a2[dn * Hh + h]);   // TEMP = 1
        g_apre[e * Hh + h] = a;
        atomicMaxFloat(&g_amax[dn * Hh + h], a);
    }
}

// ---------------- exp, z-sum, weighted aggregation (warp per edge, vector red) ----
__global__ void k_aggregate(const int* __restrict__ src, const int* __restrict__ dst) {
    int gw = (blockIdx.x * blockDim.x + threadIdx.x) >> 5;
    int lane = threadIdx.x & 31;
    if (gw >= Ee) return;
    int sn = src[gw], dn = dst[gw];
    float aexp = 0.f;
    if (lane < Hh) {
        float a = g_apre[gw * Hh + lane];
        float am = g_amax[dn * Hh + lane];
        aexp = expf(a - am);
        atomicAdd(&g_z[dn * Hh + lane], aexp);
    }
    // lane covers float4 chunk `lane` (heads 0-3) and chunk 32+lane (heads 4-7)
    float w0 = __shfl_sync(0xffffffffu, aexp, lane >> 3);
    float w1 = __shfl_sync(0xffffffffu, aexp, 4 + (lane >> 3));
    const float4* ft4 = reinterpret_cast<const float4*>(g_ft);
    float4 v0 = ft4[sn * 64 + lane];
    float4 v1 = ft4[sn * 64 + 32 + lane];
    v0.x *= w0; v0.y *= w0; v0.z *= w0; v0.w *= w0;
    v1.x *= w1; v1.y *= w1; v1.z *= w1; v1.w *= w1;
    red_add_v4(&g_agg[dn * HD + lane * 4], v0);
    red_add_v4(&g_agg[dn * HD + 128 + lane * 4], v1);
}

// ---------------- node: agg/z + residual + lrelu, accumulate BN stats ----------------
__global__ void k_node_post(const float* __restrict__ nin, float* __restrict__ ynode) {
    int c = threadIdx.x;                        // 256 (= column)
    float s = 0.f, s2 = 0.f;
    for (int n = blockIdx.x; n < Nn; n += gridDim.x) {
        float zz = g_z[n * Hh + (c >> 5)];
        if (zz == 0.f) zz = 1.f;
        float v = g_agg[n * HD + c] / zz + nin[n * HD + c];
        v = lrelu(v);
        ynode[n * HD + c] = v;
        s += v; s2 += v * v;
    }
    atomicAdd(&g_nsum[c], (double)s);
    atomicAdd(&g_nsumsq[c], (double)s2);
}

__global__ void k_node_bn(float* __restrict__ ynode,
                          const float* __restrict__ g, const float* __restrict__ b) {
    int stride = gridDim.x * blockDim.x;
    for (int i = blockIdx.x * blockDim.x + threadIdx.x; i < Nn * HD; i += stride) {
        int c = i & 255;
        float mu = (float)(g_nsum[c] / (double)Nn);
        float var = (float)(g_nsumsq[c] / (double)Nn) - mu * mu;
        float sc = rsqrtf(var + EPSB) * g[c];
        ynode[i] = (ynode[i] - mu) * sc + b[c];
    }
}

// ---------------- fused edge update (warp per edge; nf from P/Q gather) ----------
#define EU_THREADS 512
#define EU_WARPS 16
// dyn smem: W2 (64*64) + W3 (128*64) + union{ xw (16*128) | red (2048 doubles) }
#define EU_SMEM_FLOATS (64*64 + 128*64 + 4096)
__global__ void __launch_bounds__(EU_THREADS, 1)
k_edge_update(const float* __restrict__ ein,
              const float* __restrict__ W2g, const float* __restrict__ W3g,
              const int* __restrict__ src, const int* __restrict__ dst,
              float* __restrict__ yedge) {
    extern __shared__ float sm[];
    float* W2 = sm;                  // 64*64
    float* W3 = W2 + 64 * 64;        // 128*64
    float* xb = W3 + 128 * 64;       // union area (4096 floats)
    int tid = threadIdx.x;
    for (int i = tid; i < 64 * 64;  i += EU_THREADS) W2[i] = W2g[i];
    for (int i = tid; i < 128 * 64; i += EU_THREADS) W3[i] = W3g[i];
    __syncthreads();
    int wid = tid >> 5, lane = tid & 31;
    float* xw = xb + wid * 128;
    int nwarps = gridDim.x * EU_WARPS;
    int gw0 = blockIdx.x * EU_WARPS + wid;

    double s0 = 0, s1 = 0, q0 = 0, q1 = 0;

    for (int e = gw0; e < Ee; e += nwarps) {
        int sn = src[e], dn = dst[e];
        // node features: nf = lrelu(P[src] + Q[dst])
        float2 p = *(const float2*)&g_pq[sn * 128 + 2 * lane];
        float2 q = *(const float2*)&g_pq[dn * 128 + 64 + 2 * lane];
        float nf0 = lrelu(p.x + q.x), nf1 = lrelu(p.y + q.y);

        // edge features: ef = lrelu(ein @ W2), x broadcast via shuffles
        float2 er = *(const float2*)&ein[e * EDGEF + 2 * lane];
        float ef0 = 0.f, ef1 = 0.f;
        #pragma unroll
        for (int k = 0; k < 64; k++) {
            float xv = __shfl_sync(0xffffffffu, (k & 1) ? er.y : er.x, k >> 1);
            float2 w = *(const float2*)&W2[k * 64 + 2 * lane];
            ef0 += xv * w.x; ef1 += xv * w.y;
        }
        ef0 = lrelu(ef0); ef1 = lrelu(ef1);

        // stage concat(nf, ef) in warp smem
        xw[2 * lane] = nf0; xw[2 * lane + 1] = nf1;
        xw[64 + 2 * lane] = ef0; xw[64 + 2 * lane + 1] = ef1;
        __syncwarp();

        float o0 = er.x, o1 = er.y;    // residual = ein
        #pragma unroll
        for (int k = 0; k < 128; k++) {
            float xv = xw[k];
            float2 w = *(const float2*)&W3[k * 64 + 2 * lane];
            o0 += xv * w.x; o1 += xv * w.y;
        }
        o0 = lrelu(o0); o1 = lrelu(o1);
        float2 outv; outv.x = o0; outv.y = o1;
        *(float2*)&yedge[e * EOUT + 2 * lane] = outv;
        s0 += (double)o0; s1 += (double)o1;
        q0 += (double)(o0 * o0); q1 += (double)(o1 * o1);
        __syncwarp();
    }

    // block-level reduction of BN partial sums, then atomics
    __syncthreads();
    double* red = (double*)xb;       // 16 KB (full union area)
    red[wid * 128 + lane * 4 + 0] = s0;
    red[wid * 128 + lane * 4 + 1] = s1;
    red[wid * 128 + lane * 4 + 2] = q0;
    red[wid * 128 + lane * 4 + 3] = q1;
    __syncthreads();
    if (tid < 128) {
        double t = 0;
        #pragma unroll
        for (int w = 0; w < EU_WARPS; w++) t += red[w * 128 + tid];
        int l = tid >> 2, part = tid & 3;
        if (part == 0) atomicAdd(&g_esum[2 * l], t);
        else if (part == 1) atomicAdd(&g_esum[2 * l + 1], t);
        else if (part == 2) atomicAdd(&g_esumsq[2 * l], t);
        else atomicAdd(&g_esumsq[2 * l + 1], t);
    }
}

__global__ void k_edge_bn(float* __restrict__ yedge,
                          const float* __restrict__ g, const float* __restrict__ b) {
    int stride = gridDim.x * blockDim.x;
    for (long long i = blockIdx.x * blockDim.x + threadIdx.x; i < (long long)Ee * EOUT; i += stride) {
        int c = (int)(i & 63);
        float mu = (float)(g_esum[c] / (double)Ee);
        float var = (float)(g_esumsq[c] / (double)Ee) - mu * mu;
        float sc = rsqrtf(var + EPSB) * g[c];
        yedge[i] = (yedge[i] - mu) * sc + b[c];
    }
}

// ---------------- launch ----------------
extern "C" void kernel_launch(void* const* d_in, const int* in_sizes, int n_in,
                              void* d_out, int out_size) {
    const float* node_inputs = (const float*)d_in[0];
    const float* edge_inputs = (const float*)d_in[1];
    const float* fc_w        = (const float*)d_in[2];
    const float* attn_l      = (const float*)d_in[3];
    const float* attn_r      = (const float*)d_in[4];
    const float* ae_w1       = (const float*)d_in[5];
    const float* ae_b1       = (const float*)d_in[6];
    const float* ae_w2       = (const float*)d_in[7];
    const float* ae_b2       = (const float*)d_in[8];
    const float* bn_n_g      = (const float*)d_in[9];
    const float* bn_n_b      = (const float*)d_in[10];
    const float* eu_node_w   = (const float*)d_in[11];
    const float* eu_edge_w   = (const float*)d_in[12];
    const float* eu_final_w  = (const float*)d_in[13];
    const float* bn_e_g      = (const float*)d_in[14];
    const float* bn_e_b      = (const float*)d_in[15];
    const int*   src         = (const int*)d_in[16];
    const int*   dst         = (const int*)d_in[17];

    float* out_node = (float*)d_out;
    float* out_edge = out_node + (size_t)Nn * HD;

    k_init<<<4096, 256>>>();

    dim3 ggrid(HD / GTN, (Nn + GTM - 1) / GTM);
    k_gemm_ft<<<ggrid, 256>>>(node_inputs, fc_w);

    k_attn<<<(Nn * 32 + 255) / 256, 256>>>(attn_l, attn_r);

    k_edge_attn<<<(Ee + 127) / 128, 128>>>(edge_inputs, ae_w1, ae_b1, ae_w2, ae_b2, src, dst);

    k_aggregate<<<(Ee * 32 + 255) / 256, 256>>>(src, dst);

    k_node_post<<<512, 256>>>(node_inputs, out_node);
    k_node_bn<<<8192, 256>>>(out_node, bn_n_g, bn_n_b);

    dim3 pqgrid(2, (Nn + GTM - 1) / GTM);
    k_pq_gemm<<<pqgrid, 256>>>(out_node, eu_node_w);

    cudaFuncSetAttribute(k_edge_update, cudaFuncAttributeMaxDynamicSharedMemorySize,
                         EU_SMEM_FLOATS * 4);
    k_edge_update<<<444, EU_THREADS, EU_SMEM_FLOATS * 4>>>(
        edge_inputs, eu_edge_w, eu_final_w, src, dst, out_edge);

    k_edge_bn<<<8192, 256>>>(out_edge, bn_e_g, bn_e_b);
}

// round 3
// speedup vs baseline: 1.6861x; 1.0125x over previous
#include <cuda_runtime.h>
#include <math.h>

#define Nn 50000
#define Ee 400000
#define INDIM 256
#define EDGEF 64
#define OUTD 32
#define EOUT 64
#define Hh 8
#define HD 256           // Hh*OUTD
#define ALPHA 0.2f
#define EPSB 1e-5f

// ---------------- scratch (static device globals; no allocation) ----------------
__device__ float g_ft[Nn * HD];          // node projection [N,H,D]
__device__ float g_a1[Nn * Hh];
__device__ float g_a2[Nn * Hh];
__device__ float g_pq[Nn * 128];         // P (cols 0..63) | Q (cols 64..127)
__device__ float g_wn[256 * 128];        // repacked eu_node_w
__device__ float g_apre_s[Ee * Hh];      // dst-sorted attention logits
__device__ int   g_srcs[Ee];             // dst-sorted src index
__device__ int   g_pos[Ee];              // e -> sorted position
__device__ int   g_deg[Nn];
__device__ int   g_cnt[Nn];
__device__ int   g_off[Nn + 1];
__device__ int   g_bsum[128];
__device__ double g_nsum[HD], g_nsumsq[HD];
__device__ double g_esum[EOUT], g_esumsq[EOUT];

__device__ __forceinline__ float lrelu(float x) { return x > 0.f ? x : ALPHA * x; }

// ---------------- init: zero counters / stats ----------------
__global__ void k_init() {
    int stride = gridDim.x * blockDim.x;
    for (int i = blockIdx.x * blockDim.x + threadIdx.x; i < Nn; i += stride) {
        g_deg[i] = 0; g_cnt[i] = 0;
        if (i < HD)   { g_nsum[i] = 0.0; g_nsumsq[i] = 0.0; }
        if (i < EOUT) { g_esum[i] = 0.0; g_esumsq[i] = 0.0; }
    }
}

// ---------------- generic GEMM: C[M,N] = A[M,256] @ B[256,N] -----------------
#define BM 128
#define BN 128
#define BK 8
__global__ void __launch_bounds__(256, 2)
k_gemm128(const float* __restrict__ A, const float* __restrict__ B,
          float* __restrict__ C, int M, int N) {
    __shared__ float As[2][BK][BM];
    __shared__ float Bs[2][BK][BN];
    const int K = 256;
    int tid = threadIdx.x;
    int bm = blockIdx.y * BM, bn = blockIdx.x * BN;
    int arow = tid >> 1, acol = (tid & 1) * 4;
    int brow = tid >> 5, bcol = (tid & 31) * 4;
    int tm = (tid >> 4) << 3, tn = (tid & 15) << 3;
    float acc[8][8] = {};
    bool aval = (bm + arow) < M;
    float4 a4 = aval ? *(const float4*)&A[(size_t)(bm + arow) * K + acol]
                     : make_float4(0.f, 0.f, 0.f, 0.f);
    float4 b4 = *(const float4*)&B[(size_t)brow * N + bn + bcol];
    As[0][acol + 0][arow] = a4.x; As[0][acol + 1][arow] = a4.y;
    As[0][acol + 2][arow] = a4.z; As[0][acol + 3][arow] = a4.w;
    *(float4*)&Bs[0][brow][bcol] = b4;
    __syncthreads();
    int buf = 0;
    for (int k0 = BK; k0 <= K; k0 += BK) {
        if (k0 < K) {
            a4 = aval ? *(const float4*)&A[(size_t)(bm + arow) * K + k0 + acol]
                      : make_float4(0.f, 0.f, 0.f, 0.f);
            b4 = *(const float4*)&B[(size_t)(k0 + brow) * N + bn + bcol];
        }
        #pragma unroll
        for (int k = 0; k < BK; k++) {
            float ar[8], br[8];
            *(float4*)&ar[0] = *(const float4*)&As[buf][k][tm];
            *(float4*)&ar[4] = *(const float4*)&As[buf][k][tm + 4];
            *(float4*)&br[0] = *(const float4*)&Bs[buf][k][tn];
            *(float4*)&br[4] = *(const float4*)&Bs[buf][k][tn + 4];
            #pragma unroll
            for (int i = 0; i < 8; i++)
                #pragma unroll
                for (int j = 0; j < 8; j++)
                    acc[i][j] += ar[i] * br[j];
        }
        if (k0 < K) {
            int nb = buf ^ 1;
            As[nb][acol + 0][arow] = a4.x; As[nb][acol + 1][arow] = a4.y;
            As[nb][acol + 2][arow] = a4.z; As[nb][acol + 3][arow] = a4.w;
            *(float4*)&Bs[nb][brow][bcol] = b4;
        }
        __syncthreads();
        buf ^= 1;
    }
    #pragma unroll
    for (int i = 0; i < 8; i++) {
        int gm = bm + tm + i;
        if (gm < M) {
            *(float4*)&C[(size_t)gm * N + bn + tn]     = *(float4*)&acc[i][0];
            *(float4*)&C[(size_t)gm * N + bn + tn + 4] = *(float4*)&acc[i][4];
        }
    }
}

// repack eu_node_w [512,64] -> g_wn [256,128]
__global__ void k_repack(const float* __restrict__ w) {
    int i = blockIdx.x * blockDim.x + threadIdx.x;   // 32768
    if (i < 256 * 128) {
        int k = i >> 7, j = i & 127;
        g_wn[i] = (j < 64) ? w[k * 64 + j] : w[(256 + k) * 64 + (j - 64)];
    }
}

// ---------------- per-node, per-head attention scalars ----------------
__global__ void k_attn(const float* __restrict__ attn_l, const float* __restrict__ attn_r) {
    int gw = (blockIdx.x * blockDim.x + threadIdx.x) >> 5;
    int lane = threadIdx.x & 31;
    if (gw >= Nn) return;
    #pragma unroll
    for (int h = 0; h < Hh; h++) {
        float v = g_ft[gw * HD + h * OUTD + lane];
        float s1 = v * attn_l[h * OUTD + lane];
        float s2 = v * attn_r[h * OUTD + lane];
        #pragma unroll
        for (int o = 16; o; o >>= 1) {
            s1 += __shfl_down_sync(0xffffffffu, s1, o);
            s2 += __shfl_down_sync(0xffffffffu, s2, o);
        }
        if (lane == 0) { g_a1[gw * Hh + h] = s1; g_a2[gw * Hh + h] = s2; }
    }
}

// ---------------- counting sort of edges by dst ----------------
__global__ void k_hist(const int* __restrict__ dst) {
    int e = blockIdx.x * blockDim.x + threadIdx.x;
    if (e < Ee) atomicAdd(&g_deg[dst[e]], 1);
}

__global__ void k_scan1() {            // grid 98, block 512
    __shared__ int s[512];
    int tid = threadIdx.x;
    int i = blockIdx.x * 512 + tid;
    int v = (i < Nn) ? g_deg[i] : 0;
    s[tid] = v;
    __syncthreads();
    for (int o = 1; o < 512; o <<= 1) {
        int t = (tid >= o) ? s[tid - o] : 0;
        __syncthreads();
        s[tid] += t;
        __syncthreads();
    }
    if (i < Nn) g_off[i] = s[tid] - v;
    if (tid == 511) g_bsum[blockIdx.x] = s[511];
}

__global__ void k_scan2(int nb) {      // 1 block, 128 threads
    __shared__ int s[128];
    int tid = threadIdx.x;
    int v = (tid < nb) ? g_bsum[tid] : 0;
    s[tid] = v;
    __syncthreads();
    for (int o = 1; o < 128; o <<= 1) {
        int t = (tid >= o) ? s[tid - o] : 0;
        __syncthreads();
        s[tid] += t;
        __syncthreads();
    }
    if (tid < nb) g_bsum[tid] = s[tid] - v;
}

__global__ void k_scan3() {
    int stride = gridDim.x * blockDim.x;
    for (int i = blockIdx.x * blockDim.x + threadIdx.x; i < Nn; i += stride)
        g_off[i] += g_bsum[i >> 9];
    if (blockIdx.x == 0 && threadIdx.x == 0) g_off[Nn] = Ee;
}

__global__ void k_scatter(const int* __restrict__ dst) {
    int e = blockIdx.x * blockDim.x + threadIdx.x;
    if (e < Ee) {
        int d = dst[e];
        g_pos[e] = g_off[d] + atomicAdd(&g_cnt[d], 1);
    }
}

// ---------------- edge attention MLP + logits (writes sorted) ----------------
__global__ void k_edge_attn(const float* __restrict__ ein,
                            const float* __restrict__ w1, const float* __restrict__ b1,
                            const float* __restrict__ w2, const float* __restrict__ b2,
                            const int* __restrict__ src, const int* __restrict__ dst) {
    __shared__ float sx[128 * 65];
    __shared__ float sw1[EDGEF * OUTD];
    __shared__ float sw2[OUTD * Hh];
    __shared__ float sb1[OUTD];
    __shared__ float sb2[Hh];
    int tid = threadIdx.x;                      // 128
    int e0 = blockIdx.x * 128;
    for (int i = tid; i < EDGEF * OUTD; i += 128) sw1[i] = w1[i];
    for (int i = tid; i < OUTD * Hh; i += 128) sw2[i] = w2[i];
    if (tid < OUTD) sb1[tid] = b1[tid];
    if (tid < Hh)   sb2[tid] = b2[tid];
    for (int i = tid; i < 128 * EDGEF; i += 128) {
        int r = i >> 6, c = i & 63;
        int e = e0 + r;
        sx[r * 65 + c] = (e < Ee) ? ein[e * EDGEF + c] : 0.f;
    }
    __syncthreads();
    int e = e0 + tid;
    if (e >= Ee) return;
    const float* x = &sx[tid * 65];
    float acc[Hh];
    #pragma unroll
    for (int h = 0; h < Hh; h++) acc[h] = sb2[h];
    for (int i = 0; i < OUTD; i++) {
        float s = sb1[i];
        #pragma unroll
        for (int k = 0; k < EDGEF; k++) s += x[k] * sw1[k * OUTD + i];
        s = lrelu(s);
        #pragma unroll
        for (int h = 0; h < Hh; h++) acc[h] += s * sw2[i * Hh + h];
    }
    int sn = src[e], dn = dst[e];
    int pos = g_pos[e];
    g_srcs[pos] = sn;
    #pragma unroll
    for (int h = 0; h < Hh; h++) {
        float a = lrelu(acc[h] + g_a1[sn * Hh + h] + g_a2[dn * Hh + h]);   // TEMP = 1
        g_apre_s[pos * 8 + h] = a;
    }
}

// ---------------- fused: softmax + aggregate + residual + lrelu + BN stats -------
__global__ void __launch_bounds__(256)
k_agg_fused(const float* __restrict__ nin, float* __restrict__ ynode) {
    int lane = threadIdx.x & 31;
    int wid = (blockIdx.x * blockDim.x + threadIdx.x) >> 5;
    int nw = (gridDim.x * blockDim.x) >> 5;
    float s[8] = {}, s2[8] = {};
    for (int n = wid; n < Nn; n += nw) {
        int start = g_off[n], end = g_off[n + 1];
        int deg = end - start;
        float acc[8] = {};
        float zz = 0.f;
        if (deg > 0) {
            // pass 1: per-head max (lane -> (sub=lane>>3, head=lane&7))
            float am = -INFINITY;
            int h = lane & 7, sub = lane >> 3;
            for (int i = sub; i < deg; i += 4)
                am = fmaxf(am, g_apre_s[(start + i) * 8 + h]);
            am = fmaxf(am, __shfl_xor_sync(0xffffffffu, am, 8));
            am = fmaxf(am, __shfl_xor_sync(0xffffffffu, am, 16));
            // pass 2: exp, z, weighted gather-sum
            for (int i = 0; i < deg; i++) {
                int sn = g_srcs[start + i];
                float w = 0.f;
                if (lane < 8) {
                    w = __expf(g_apre_s[(start + i) * 8 + lane] - am);
                    zz += w;
                }
                const float* ftr = &g_ft[(size_t)sn * HD + lane];
                #pragma unroll
                for (int j = 0; j < 8; j++) {
                    float wj = __shfl_sync(0xffffffffu, w, j);
                    acc[j] += wj * ftr[j * 32];
                }
            }
        }
        #pragma unroll
        for (int j = 0; j < 8; j++) {
            float zj = __shfl_sync(0xffffffffu, zz, j);
            if (zj == 0.f) zj = 1.f;
            float v = acc[j] / zj + nin[(size_t)n * HD + j * 32 + lane];
            v = lrelu(v);
            ynode[(size_t)n * HD + j * 32 + lane] = v;
            s[j] += v; s2[j] += v * v;
        }
    }
    // block reduce BN partials (all warps share the same column mapping)
    __shared__ float red[8][512];
    int w = threadIdx.x >> 5;
    #pragma unroll
    for (int j = 0; j < 8; j++) {
        red[w][j * 32 + lane] = s[j];
        red[w][256 + j * 32 + lane] = s2[j];
    }
    __syncthreads();
    if (threadIdx.x < 256) {
        float ts = 0.f, ts2 = 0.f;
        #pragma unroll
        for (int ww = 0; ww < 8; ww++) { ts += red[ww][threadIdx.x]; ts2 += red[ww][256 + threadIdx.x]; }
        atomicAdd(&g_nsum[threadIdx.x], (double)ts);
        atomicAdd(&g_nsumsq[threadIdx.x], (double)ts2);
    }
}

__global__ void k_node_bn(float* __restrict__ ynode,
                          const float* __restrict__ g, const float* __restrict__ b) {
    int stride = gridDim.x * blockDim.x;
    for (int i = blockIdx.x * blockDim.x + threadIdx.x; i < Nn * HD; i += stride) {
        int c = i & 255;
        float mu = (float)(g_nsum[c] / (double)Nn);
        float var = (float)(g_nsumsq[c] / (double)Nn) - mu * mu;
        float sc = rsqrtf(var + EPSB) * g[c];
        ynode[i] = (ynode[i] - mu) * sc + b[c];
    }
}

// ---------------- fused edge update (warp per edge; nf from P/Q gather) ----------
#define EU_THREADS 512
#define EU_WARPS 16
#define EU_SMEM_FLOATS (64*64 + 128*64 + 4096)
__global__ void __launch_bounds__(EU_THREADS, 1)
k_edge_update(const float* __restrict__ ein,
              const float* __restrict__ W2g, const float* __restrict__ W3g,
              const int* __restrict__ src, const int* __restrict__ dst,
              float* __restrict__ yedge) {
    extern __shared__ float sm[];
    float* W2 = sm;                  // 64*64
    float* W3 = W2 + 64 * 64;        // 128*64
    float* xb = W3 + 128 * 64;       // union area (4096 floats)
    int tid = threadIdx.x;
    for (int i = tid; i < 64 * 64;  i += EU_THREADS) W2[i] = W2g[i];
    for (int i = tid; i < 128 * 64; i += EU_THREADS) W3[i] = W3g[i];
    __syncthreads();
    int wid = tid >> 5, lane = tid & 31;
    float* xw = xb + wid * 128;
    int nwarps = gridDim.x * EU_WARPS;
    int gw0 = blockIdx.x * EU_WARPS + wid;

    double s0 = 0, s1 = 0, q0 = 0, q1 = 0;

    for (int e = gw0; e < Ee; e += nwarps) {
        int sn = src[e], dn = dst[e];
        float2 p = *(const float2*)&g_pq[sn * 128 + 2 * lane];
        float2 q = *(const float2*)&g_pq[dn * 128 + 64 + 2 * lane];
        float nf0 = lrelu(p.x + q.x), nf1 = lrelu(p.y + q.y);

        float2 er = *(const float2*)&ein[e * EDGEF + 2 * lane];
        float ef0 = 0.f, ef1 = 0.f;
        #pragma unroll
        for (int k = 0; k < 64; k++) {
            float xv = __shfl_sync(0xffffffffu, (k & 1) ? er.y : er.x, k >> 1);
            float2 w = *(const float2*)&W2[k * 64 + 2 * lane];
            ef0 += xv * w.x; ef1 += xv * w.y;
        }
        ef0 = lrelu(ef0); ef1 = lrelu(ef1);

        xw[2 * lane] = nf0; xw[2 * lane + 1] = nf1;
        xw[64 + 2 * lane] = ef0; xw[64 + 2 * lane + 1] = ef1;
        __syncwarp();

        float o0 = er.x, o1 = er.y;    // residual = ein
        #pragma unroll
        for (int k = 0; k < 128; k++) {
            float xv = xw[k];
            float2 w = *(const float2*)&W3[k * 64 + 2 * lane];
            o0 += xv * w.x; o1 += xv * w.y;
        }
        o0 = lrelu(o0); o1 = lrelu(o1);
        float2 outv; outv.x = o0; outv.y = o1;
        *(float2*)&yedge[e * EOUT + 2 * lane] = outv;
        s0 += (double)o0; s1 += (double)o1;
        q0 += (double)(o0 * o0); q1 += (double)(o1 * o1);
        __syncwarp();
    }

    __syncthreads();
    double* red = (double*)xb;
    red[wid * 128 + lane * 4 + 0] = s0;
    red[wid * 128 + lane * 4 + 1] = s1;
    red[wid * 128 + lane * 4 + 2] = q0;
    red[wid * 128 + lane * 4 + 3] = q1;
    __syncthreads();
    if (tid < 128) {
        double t = 0;
        #pragma unroll
        for (int w = 0; w < EU_WARPS; w++) t += red[w * 128 + tid];
        int l = tid >> 2, part = tid & 3;
        if (part == 0) atomicAdd(&g_esum[2 * l], t);
        else if (part == 1) atomicAdd(&g_esum[2 * l + 1], t);
        else if (part == 2) atomicAdd(&g_esumsq[2 * l], t);
        else atomicAdd(&g_esumsq[2 * l + 1], t);
    }
}

__global__ void k_edge_bn(float* __restrict__ yedge,
                          const float* __restrict__ g, const float* __restrict__ b) {
    int stride = gridDim.x * blockDim.x;
    for (long long i = blockIdx.x * blockDim.x + threadIdx.x; i < (long long)Ee * EOUT; i += stride) {
        int c = (int)(i & 63);
        float mu = (float)(g_esum[c] / (double)Ee);
        float var = (float)(g_esumsq[c] / (double)Ee) - mu * mu;
        float sc = rsqrtf(var + EPSB) * g[c];
        yedge[i] = (yedge[i] - mu) * sc + b[c];
    }
}

// ---------------- launch ----------------
extern "C" void kernel_launch(void* const* d_in, const int* in_sizes, int n_in,
                              void* d_out, int out_size) {
    const float* node_inputs = (const float*)d_in[0];
    const float* edge_inputs = (const float*)d_in[1];
    const float* fc_w        = (const float*)d_in[2];
    const float* attn_l      = (const float*)d_in[3];
    const float* attn_r      = (const float*)d_in[4];
    const float* ae_w1       = (const float*)d_in[5];
    const float* ae_b1       = (const float*)d_in[6];
    const float* ae_w2       = (const float*)d_in[7];
    const float* ae_b2       = (const float*)d_in[8];
    const float* bn_n_g      = (const float*)d_in[9];
    const float* bn_n_b      = (const float*)d_in[10];
    const float* eu_node_w   = (const float*)d_in[11];
    const float* eu_edge_w   = (const float*)d_in[12];
    const float* eu_final_w  = (const float*)d_in[13];
    const float* bn_e_g      = (const float*)d_in[14];
    const float* bn_e_b      = (const float*)d_in[15];
    const int*   src         = (const int*)d_in[16];
    const int*   dst         = (const int*)d_in[17];

    float* out_node = (float*)d_out;
    float* out_edge = out_node + (size_t)Nn * HD;

    float* d_ft; cudaGetSymbolAddress((void**)&d_ft, g_ft);
    float* d_pq; cudaGetSymbolAddress((void**)&d_pq, g_pq);
    float* d_wn; cudaGetSymbolAddress((void**)&d_wn, g_wn);

    k_init<<<256, 256>>>();

    dim3 ggrid(HD / BN, (Nn + BM - 1) / BM);
    k_gemm128<<<ggrid, 256>>>(node_inputs, fc_w, d_ft, Nn, HD);

    k_attn<<<(Nn * 32 + 255) / 256, 256>>>(attn_l, attn_r);

    k_hist<<<(Ee + 255) / 256, 256>>>(dst);
    k_scan1<<<(Nn + 511) / 512, 512>>>();
    k_scan2<<<1, 128>>>((Nn + 511) / 512);
    k_scan3<<<128, 256>>>();
    k_scatter<<<(Ee + 255) / 256, 256>>>(dst);

    k_edge_attn<<<(Ee + 127) / 128, 128>>>(edge_inputs, ae_w1, ae_b1, ae_w2, ae_b2, src, dst);

    k_agg_fused<<<592, 256>>>(node_inputs, out_node);
    k_node_bn<<<8192, 256>>>(out_node, bn_n_g, bn_n_b);

    k_repack<<<128, 256>>>(eu_node_w);
    dim3 pqgrid(1, (Nn + BM - 1) / BM);
    k_gemm128<<<pqgrid, 256>>>(out_node, d_wn, d_pq, Nn, 128);

    cudaFuncSetAttribute(k_edge_update, cudaFuncAttributeMaxDynamicSharedMemorySize,
                         EU_SMEM_FLOATS * 4);
    k_edge_update<<<444, EU_THREADS, EU_SMEM_FLOATS * 4>>>(
        edge_inputs, eu_edge_w, eu_final_w, src, dst, out_edge);

    k_edge_bn<<<8192, 256>>>(out_edge, bn_e_g, bn_e_b);
}

// round 4
// speedup vs baseline: 4.7877x; 2.8395x over previous
#include <cuda_runtime.h>
#include <math.h>

#define Nn 50000
#define Ee 400000
#define INDIM 256
#define EDGEF 64
#define OUTD 32
#define EOUT 64
#define Hh 8
#define HD 256           // Hh*OUTD
#define ALPHA 0.2f
#define EPSB 1e-5f

// ---------------- scratch (static device globals; no allocation) ----------------
__device__ float g_ft[Nn * HD];          // node projection [N,H,D]
__device__ float g_a1[Nn * Hh];
__device__ float g_a2[Nn * Hh];
__device__ float g_pq[Nn * 128];         // P (cols 0..63) | Q (cols 64..127)
__device__ float g_wn[256 * 128];        // repacked eu_node_w
__device__ float g_apre_s[Ee * Hh];      // dst-sorted attention logits
__device__ int   g_srcs[Ee];             // dst-sorted src index
__device__ int   g_pos[Ee];              // e -> sorted position
__device__ int   g_deg[Nn];
__device__ int   g_cnt[Nn];
__device__ int   g_off[Nn + 1];
__device__ int   g_bsum[128];
__device__ double g_nsum[HD], g_nsumsq[HD];
__device__ double g_esum[EOUT], g_esumsq[EOUT];
__device__ float g_nsc[HD], g_nsh[HD];
__device__ float g_esc[EOUT], g_esh[EOUT];

__device__ __forceinline__ float lrelu(float x) { return x > 0.f ? x : ALPHA * x; }

// ---------------- init: zero counters / stats ----------------
__global__ void k_init() {
    int stride = gridDim.x * blockDim.x;
    for (int i = blockIdx.x * blockDim.x + threadIdx.x; i < Nn; i += stride) {
        g_deg[i] = 0; g_cnt[i] = 0;
        if (i < HD)   { g_nsum[i] = 0.0; g_nsumsq[i] = 0.0; }
        if (i < EOUT) { g_esum[i] = 0.0; g_esumsq[i] = 0.0; }
    }
}

// ---------------- generic GEMM: C[M,N] = A[M,256] @ B[256,N] -----------------
#define BM 128
#define BN 128
#define BK 8
__global__ void __launch_bounds__(256, 2)
k_gemm128(const float* __restrict__ A, const float* __restrict__ B,
          float* __restrict__ C, int M, int N) {
    __shared__ float As[2][BK][BM];
    __shared__ float Bs[2][BK][BN];
    const int K = 256;
    int tid = threadIdx.x;
    int bm = blockIdx.y * BM, bn = blockIdx.x * BN;
    int arow = tid >> 1, acol = (tid & 1) * 4;
    int brow = tid >> 5, bcol = (tid & 31) * 4;
    int tm = (tid >> 4) << 3, tn = (tid & 15) << 3;
    float acc[8][8] = {};
    bool aval = (bm + arow) < M;
    float4 a4 = aval ? *(const float4*)&A[(size_t)(bm + arow) * K + acol]
                     : make_float4(0.f, 0.f, 0.f, 0.f);
    float4 b4 = *(const float4*)&B[(size_t)brow * N + bn + bcol];
    As[0][acol + 0][arow] = a4.x; As[0][acol + 1][arow] = a4.y;
    As[0][acol + 2][arow] = a4.z; As[0][acol + 3][arow] = a4.w;
    *(float4*)&Bs[0][brow][bcol] = b4;
    __syncthreads();
    int buf = 0;
    for (int k0 = BK; k0 <= K; k0 += BK) {
        if (k0 < K) {
            a4 = aval ? *(const float4*)&A[(size_t)(bm + arow) * K + k0 + acol]
                      : make_float4(0.f, 0.f, 0.f, 0.f);
            b4 = *(const float4*)&B[(size_t)(k0 + brow) * N + bn + bcol];
        }
        #pragma unroll
        for (int k = 0; k < BK; k++) {
            float ar[8], br[8];
            *(float4*)&ar[0] = *(const float4*)&As[buf][k][tm];
            *(float4*)&ar[4] = *(const float4*)&As[buf][k][tm + 4];
            *(float4*)&br[0] = *(const float4*)&Bs[buf][k][tn];
            *(float4*)&br[4] = *(const float4*)&Bs[buf][k][tn + 4];
            #pragma unroll
            for (int i = 0; i < 8; i++)
                #pragma unroll
                for (int j = 0; j < 8; j++)
                    acc[i][j] += ar[i] * br[j];
        }
        if (k0 < K) {
            int nb = buf ^ 1;
            As[nb][acol + 0][arow] = a4.x; As[nb][acol + 1][arow] = a4.y;
            As[nb][acol + 2][arow] = a4.z; As[nb][acol + 3][arow] = a4.w;
            *(float4*)&Bs[nb][brow][bcol] = b4;
        }
        __syncthreads();
        buf ^= 1;
    }
    #pragma unroll
    for (int i = 0; i < 8; i++) {
        int gm = bm + tm + i;
        if (gm < M) {
            *(float4*)&C[(size_t)gm * N + bn + tn]     = *(float4*)&acc[i][0];
            *(float4*)&C[(size_t)gm * N + bn + tn + 4] = *(float4*)&acc[i][4];
        }
    }
}

// repack eu_node_w [512,64] -> g_wn [256,128]
__global__ void k_repack(const float* __restrict__ w) {
    int i = blockIdx.x * blockDim.x + threadIdx.x;
    if (i < 256 * 128) {
        int k = i >> 7, j = i & 127;
        g_wn[i] = (j < 64) ? w[k * 64 + j] : w[(256 + k) * 64 + (j - 64)];
    }
}

// ---------------- per-node, per-head attention scalars (warp/node) --------------
__global__ void k_attn(const float* __restrict__ al, const float* __restrict__ ar) {
    int gw = (blockIdx.x * blockDim.x + threadIdx.x) >> 5;
    int lane = threadIdx.x & 31;
    int h = lane >> 2, p = lane & 3;
    float4 al0 = __ldg((const float4*)&al[h * 32 + p * 4]);
    float4 al1 = __ldg((const float4*)&al[h * 32 + 16 + p * 4]);
    float4 ar0 = __ldg((const float4*)&ar[h * 32 + p * 4]);
    float4 ar1 = __ldg((const float4*)&ar[h * 32 + 16 + p * 4]);
    if (gw >= Nn) return;
    const float4* f = (const float4*)&g_ft[(size_t)gw * HD];
    float4 f0 = f[h * 8 + p], f1 = f[h * 8 + 4 + p];
    float s1 = f0.x * al0.x + f0.y * al0.y + f0.z * al0.z + f0.w * al0.w
             + f1.x * al1.x + f1.y * al1.y + f1.z * al1.z + f1.w * al1.w;
    float s2 = f0.x * ar0.x + f0.y * ar0.y + f0.z * ar0.z + f0.w * ar0.w
             + f1.x * ar1.x + f1.y * ar1.y + f1.z * ar1.z + f1.w * ar1.w;
    s1 += __shfl_xor_sync(0xffffffffu, s1, 1); s1 += __shfl_xor_sync(0xffffffffu, s1, 2);
    s2 += __shfl_xor_sync(0xffffffffu, s2, 1); s2 += __shfl_xor_sync(0xffffffffu, s2, 2);
    if (p == 0) { g_a1[gw * Hh + h] = s1; g_a2[gw * Hh + h] = s2; }
}

// ---------------- counting sort of edges by dst ----------------
__global__ void k_hist(const int* __restrict__ dst) {
    int e = blockIdx.x * blockDim.x + threadIdx.x;
    if (e < Ee) atomicAdd(&g_deg[dst[e]], 1);
}

__global__ void k_scan1() {
    __shared__ int s[512];
    int tid = threadIdx.x;
    int i = blockIdx.x * 512 + tid;
    int v = (i < Nn) ? g_deg[i] : 0;
    s[tid] = v;
    __syncthreads();
    for (int o = 1; o < 512; o <<= 1) {
        int t = (tid >= o) ? s[tid - o] : 0;
        __syncthreads();
        s[tid] += t;
        __syncthreads();
    }
    if (i < Nn) g_off[i] = s[tid] - v;
    if (tid == 511) g_bsum[blockIdx.x] = s[511];
}

__global__ void k_scan2(int nb) {
    __shared__ int s[128];
    int tid = threadIdx.x;
    int v = (tid < nb) ? g_bsum[tid] : 0;
    s[tid] = v;
    __syncthreads();
    for (int o = 1; o < 128; o <<= 1) {
        int t = (tid >= o) ? s[tid - o] : 0;
        __syncthreads();
        s[tid] += t;
        __syncthreads();
    }
    if (tid < nb) g_bsum[tid] = s[tid] - v;
}

__global__ void k_scan3() {
    int stride = gridDim.x * blockDim.x;
    for (int i = blockIdx.x * blockDim.x + threadIdx.x; i < Nn; i += stride)
        g_off[i] += g_bsum[i >> 9];
    if (blockIdx.x == 0 && threadIdx.x == 0) g_off[Nn] = Ee;
}

__global__ void k_scatter(const int* __restrict__ dst) {
    int e = blockIdx.x * blockDim.x + threadIdx.x;
    if (e < Ee) {
        int d = dst[e];
        g_pos[e] = g_off[d] + atomicAdd(&g_cnt[d], 1);
    }
}

// ---------------- edge attention MLP (register-tiled), writes sorted ------------
// block: 256 threads, 128 edges. dyn smem: sx[64][130] + sw1[2048] + sh[128][36]
#define EA_SX (64 * 130)
#define EA_SW (64 * 32)
#define EA_SH (128 * 36)
#define EA_SMEM_FLOATS (EA_SX + EA_SW + EA_SH)
__global__ void __launch_bounds__(256)
k_edge_attn(const float* __restrict__ ein,
            const float* __restrict__ w1, const float* __restrict__ b1,
            const float* __restrict__ w2, const float* __restrict__ b2,
            const int* __restrict__ src, const int* __restrict__ dst) {
    extern __shared__ float sm[];
    float* sx  = sm;                 // [k][edge] stride 130
    float* sw1 = sx + EA_SX;         // [k][i] 64x32
    float* sh  = sw1 + EA_SW;        // [edge][hidden] stride 36
    int tid = threadIdx.x;
    int e0 = blockIdx.x * 128;       // Ee % 128 == 0

    for (int i = tid; i < EA_SW; i += 256) sw1[i] = w1[i];
    for (int i = tid; i < 128 * 64; i += 256) {
        int r = i >> 6, c = i & 63;
        sx[c * 130 + r] = ein[(size_t)(e0 + r) * EDGEF + c];
    }
    __syncthreads();

    // layer 1: thread = 2 edges x 8 hidden
    {
        int hg = tid >> 6;           // 0..3
        int ep = tid & 63;           // edge pair
        float4 bb0 = __ldg((const float4*)&b1[hg * 8]);
        float4 bb1 = __ldg((const float4*)&b1[hg * 8 + 4]);
        float acc0[8], acc1[8];
        acc0[0] = bb0.x; acc0[1] = bb0.y; acc0[2] = bb0.z; acc0[3] = bb0.w;
        acc0[4] = bb1.x; acc0[5] = bb1.y; acc0[6] = bb1.z; acc0[7] = bb1.w;
        #pragma unroll
        for (int j = 0; j < 8; j++) acc1[j] = acc0[j];
        #pragma unroll 4
        for (int k = 0; k < 64; k++) {
            float2 a = *(const float2*)&sx[k * 130 + 2 * ep];
            float4 w0 = *(const float4*)&sw1[k * 32 + hg * 8];
            float4 w1v = *(const float4*)&sw1[k * 32 + hg * 8 + 4];
            float wv[8] = {w0.x, w0.y, w0.z, w0.w, w1v.x, w1v.y, w1v.z, w1v.w};
            #pragma unroll
            for (int j = 0; j < 8; j++) {
                acc0[j] += a.x * wv[j];
                acc1[j] += a.y * wv[j];
            }
        }
        float* h0 = &sh[(2 * ep) * 36 + hg * 8];
        float* h1 = &sh[(2 * ep + 1) * 36 + hg * 8];
        #pragma unroll
        for (int j = 0; j < 8; j++) { h0[j] = lrelu(acc0[j]); h1[j] = lrelu(acc1[j]); }
    }
    __syncthreads();

    // layer 2 + epilogue: thread = 1 edge-half (4 heads)
    {
        int el = tid >> 1, half = tid & 1, hs = half * 4;
        int e = e0 + el;
        float4 bb = __ldg((const float4*)&b2[0]);
        float acc[4];
        if (hs == 0) { acc[0] = bb.x; acc[1] = bb.y; acc[2] = bb.z; acc[3] = bb.w; }
        else { bb = __ldg((const float4*)&b2[4]); acc[0] = bb.x; acc[1] = bb.y; acc[2] = bb.z; acc[3] = bb.w; }
        const float* hrow = &sh[el * 36];
        #pragma unroll 8
        for (int i = 0; i < 32; i++) {
            float s = hrow[i];
            float4 w = __ldg((const float4*)&w2[i * 8 + hs]);
            acc[0] += s * w.x; acc[1] += s * w.y; acc[2] += s * w.z; acc[3] += s * w.w;
        }
        int sn = src[e], dn = dst[e];
        int pos = g_pos[e];
        if (half == 0) g_srcs[pos] = sn;
        float4 A1 = *(const float4*)&g_a1[sn * 8 + hs];
        float4 A2 = *(const float4*)&g_a2[dn * 8 + hs];
        float4 o;
        o.x = lrelu(acc[0] + A1.x + A2.x);
        o.y = lrelu(acc[1] + A1.y + A2.y);
        o.z = lrelu(acc[2] + A1.z + A2.z);
        o.w = lrelu(acc[3] + A1.w + A2.w);
        *(float4*)&g_apre_s[(size_t)pos * 8 + hs] = o;
    }
}

// ---------------- fused: softmax + aggregate + residual + lrelu + BN stats -------
__global__ void __launch_bounds__(256)
k_agg_fused(const float* __restrict__ nin, float* __restrict__ ynode) {
    int lane = threadIdx.x & 31;
    int wid = (blockIdx.x * blockDim.x + threadIdx.x) >> 5;
    int nw = (gridDim.x * blockDim.x) >> 5;
    int sub = lane >> 3, h = lane & 7;
    float s[8] = {}, s2[8] = {};
    for (int n = wid; n < Nn; n += nw) {
        int start = g_off[n], end = g_off[n + 1];
        int deg = end - start;
        float acc[8] = {};
        float zz = 0.f;
        if (deg > 0) {
            // pass 1: per-head max
            float am = -INFINITY;
            for (int i = sub; i < deg; i += 4)
                am = fmaxf(am, g_apre_s[(size_t)(start + i) * 8 + h]);
            am = fmaxf(am, __shfl_xor_sync(0xffffffffu, am, 8));
            am = fmaxf(am, __shfl_xor_sync(0xffffffffu, am, 16));
            // pass 2: 4 edges per iteration
            for (int i = 0; i < deg; i += 4) {
                float w = 0.f;
                if (i + sub < deg)
                    w = __expf(g_apre_s[(size_t)(start + i + sub) * 8 + h] - am);
                zz += w;
                int sn4 = 0;
                if (lane < 4 && i + lane < deg) sn4 = g_srcs[start + i + lane];
                #pragma unroll
                for (int e = 0; e < 4; e++) {
                    int sn = __shfl_sync(0xffffffffu, sn4, e);
                    const float* ftr = &g_ft[(size_t)sn * HD + lane];
                    #pragma unroll
                    for (int j = 0; j < 8; j++) {
                        float wj = __shfl_sync(0xffffffffu, w, e * 8 + j);
                        acc[j] += wj * ftr[j * 32];
                    }
                }
            }
            zz += __shfl_xor_sync(0xffffffffu, zz, 8);
            zz += __shfl_xor_sync(0xffffffffu, zz, 16);
        }
        #pragma unroll
        for (int j = 0; j < 8; j++) {
            float zj = __shfl_sync(0xffffffffu, zz, j);
            if (zj == 0.f) zj = 1.f;
            float v = acc[j] / zj + nin[(size_t)n * HD + j * 32 + lane];
            v = lrelu(v);
            ynode[(size_t)n * HD + j * 32 + lane] = v;
            s[j] += v; s2[j] += v * v;
        }
    }
    __shared__ float red[8][512];
    int w = threadIdx.x >> 5;
    #pragma unroll
    for (int j = 0; j < 8; j++) {
        red[w][j * 32 + lane] = s[j];
        red[w][256 + j * 32 + lane] = s2[j];
    }
    __syncthreads();
    if (threadIdx.x < 256) {
        float ts = 0.f, ts2 = 0.f;
        #pragma unroll
        for (int ww = 0; ww < 8; ww++) { ts += red[ww][threadIdx.x]; ts2 += red[ww][256 + threadIdx.x]; }
        atomicAdd(&g_nsum[threadIdx.x], (double)ts);
        atomicAdd(&g_nsumsq[threadIdx.x], (double)ts2);
    }
}

// ---------------- BN prep (fp64 once per column) ----------------
__global__ void k_bn_prep_node(const float* __restrict__ g, const float* __restrict__ b) {
    int c = threadIdx.x;
    double mu = g_nsum[c] / (double)Nn;
    double var = g_nsumsq[c] / (double)Nn - mu * mu;
    float sc = rsqrtf((float)var + EPSB) * g[c];
    g_nsc[c] = sc;
    g_nsh[c] = b[c] - (float)mu * sc;
}
__global__ void k_bn_prep_edge(const float* __restrict__ g, const float* __restrict__ b) {
    int c = threadIdx.x;
    double mu = g_esum[c] / (double)Ee;
    double var = g_esumsq[c] / (double)Ee - mu * mu;
    float sc = rsqrtf((float)var + EPSB) * g[c];
    g_esc[c] = sc;
    g_esh[c] = b[c] - (float)mu * sc;
}

__global__ void k_node_bn(float* __restrict__ ynode) {
    int i = blockIdx.x * blockDim.x + threadIdx.x;   // float4 index
    if (i < Nn * HD / 4) {
        int cb = (i & 63) * 4;
        float4 v = ((float4*)ynode)[i];
        float4 sc = *(const float4*)&g_nsc[cb];
        float4 sh = *(const float4*)&g_nsh[cb];
        v.x = v.x * sc.x + sh.x; v.y = v.y * sc.y + sh.y;
        v.z = v.z * sc.z + sh.z; v.w = v.w * sc.w + sh.w;
        ((float4*)ynode)[i] = v;
    }
}

__global__ void k_edge_bn(float* __restrict__ yedge) {
    int i = blockIdx.x * blockDim.x + threadIdx.x;
    if (i < Ee * EOUT / 4) {
        int cb = (i & 15) * 4;
        float4 v = ((float4*)yedge)[i];
        float4 sc = *(const float4*)&g_esc[cb];
        float4 sh = *(const float4*)&g_esh[cb];
        v.x = v.x * sc.x + sh.x; v.y = v.y * sc.y + sh.y;
        v.z = v.z * sc.z + sh.z; v.w = v.w * sc.w + sh.w;
        ((float4*)yedge)[i] = v;
    }
}

// ---------------- edge update MLP: 4 edges per warp per iteration ----------------
#define EU_THREADS 256
#define EU_WARPS 8
// smem floats: W2 4096 + W3 8192 + per-warp stage (se 256 + xw 512) * 8
#define EU_STAGE (EU_WARPS * 768)
#define EU_SMEM_FLOATS (4096 + 8192 + EU_STAGE)
__global__ void __launch_bounds__(EU_THREADS)
k_edge_update(const float* __restrict__ ein,
              const float* __restrict__ W2g, const float* __restrict__ W3g,
              const int* __restrict__ src, const int* __restrict__ dst,
              float* __restrict__ yedge) {
    extern __shared__ float sm[];
    float* W2 = sm;                  // [k][out] 64x64
    float* W3 = W2 + 4096;           // [k][out] 128x64
    float* stage = W3 + 8192;
    int tid = threadIdx.x;
    for (int i = tid; i < 4096; i += EU_THREADS) W2[i] = W2g[i];
    for (int i = tid; i < 8192; i += EU_THREADS) W3[i] = W3g[i];
    __syncthreads();
    int wid = tid >> 5, lane = tid & 31;
    float* se = stage + wid * 768;   // 4 x 64
    float* xw = se + 256;            // 4 x 128
    int nwarps = gridDim.x * EU_WARPS;
    int gw0 = blockIdx.x * EU_WARPS + wid;
    const int NG = Ee / 4;           // 100000 groups

    float s0 = 0.f, s1 = 0.f, q0 = 0.f, q1 = 0.f;

    for (int g = gw0; g < NG; g += nwarps) {
        int base = g * 4;
        float2 er[4];
        float nfx[4], nfy[4];
        #pragma unroll
        for (int e = 0; e < 4; e++) {
            int sn = src[base + e], dn = dst[base + e];
            er[e] = *(const float2*)&ein[(size_t)(base + e) * EDGEF + 2 * lane];
            float2 p = *(const float2*)&g_pq[(size_t)sn * 128 + 2 * lane];
            float2 q = *(const float2*)&g_pq[(size_t)dn * 128 + 64 + 2 * lane];
            nfx[e] = lrelu(p.x + q.x);
            nfy[e] = lrelu(p.y + q.y);
            *(float2*)&se[e * 64 + 2 * lane] = er[e];
            float2 nf2; nf2.x = nfx[e]; nf2.y = nfy[e];
            *(float2*)&xw[e * 128 + 2 * lane] = nf2;
        }
        __syncwarp();

        // ef = lrelu(ein @ W2)
        float efx[4] = {}, efy[4] = {};
        #pragma unroll 4
        for (int k0 = 0; k0 < 64; k0 += 4) {
            float4 xv[4];
            #pragma unroll
            for (int e = 0; e < 4; e++) xv[e] = *(const float4*)&se[e * 64 + k0];
            #pragma unroll
            for (int j = 0; j < 4; j++) {
                float2 w = *(const float2*)&W2[(k0 + j) * 64 + 2 * lane];
                float xj[4] = {((const float*)&xv[0])[j], ((const float*)&xv[1])[j],
                               ((const float*)&xv[2])[j], ((const float*)&xv[3])[j]};
                #pragma unroll
                for (int e = 0; e < 4; e++) { efx[e] += xj[e] * w.x; efy[e] += xj[e] * w.y; }
            }
        }
        #pragma unroll
        for (int e = 0; e < 4; e++) {
            float2 ef2; ef2.x = lrelu(efx[e]); ef2.y = lrelu(efy[e]);
            *(float2*)&xw[e * 128 + 64 + 2 * lane] = ef2;
        }
        __syncwarp();

        // o = concat(nf, ef) @ W3 + ein residual
        float ox[4], oy[4];
        #pragma unroll
        for (int e = 0; e < 4; e++) { ox[e] = er[e].x; oy[e] = er[e].y; }
        #pragma unroll 4
        for (int k0 = 0; k0 < 128; k0 += 4) {
            float4 xv[4];
            #pragma unroll
            for (int e = 0; e < 4; e++) xv[e] = *(const float4*)&xw[e * 128 + k0];
            #pragma unroll
            for (int j = 0; j < 4; j++) {
                float2 w = *(const float2*)&W3[(k0 + j) * 64 + 2 * lane];
                float xj[4] = {((const float*)&xv[0])[j], ((const float*)&xv[1])[j],
                               ((const float*)&xv[2])[j], ((const float*)&xv[3])[j]};
                #pragma unroll
                for (int e = 0; e < 4; e++) { ox[e] += xj[e] * w.x; oy[e] += xj[e] * w.y; }
            }
        }
        #pragma unroll
        for (int e = 0; e < 4; e++) {
            float a = lrelu(ox[e]), b = lrelu(oy[e]);
            float2 outv; outv.x = a; outv.y = b;
            *(float2*)&yedge[(size_t)(base + e) * EOUT + 2 * lane] = outv;
            s0 += a; s1 += b; q0 += a * a; q1 += b * b;
        }
        __syncwarp();
    }

    // block-level reduction of BN partials
    __syncthreads();
    float* red = stage;              // 8 warps x 128 floats x ... reuse
    red[wid * 512 + lane * 4 + 0] = s0;
    red[wid * 512 + lane * 4 + 1] = s1;
    red[wid * 512 + lane * 4 + 2] = q0;
    red[wid * 512 + lane * 4 + 3] = q1;
    __syncthreads();
    if (tid < 128) {
        float t = 0.f;
        #pragma unroll
        for (int w = 0; w < EU_WARPS; w++) t += red[w * 512 + tid];
        int l = tid >> 2, part = tid & 3;
        if (part == 0) atomicAdd(&g_esum[2 * l], (double)t);
        else if (part == 1) atomicAdd(&g_esum[2 * l + 1], (double)t);
        else if (part == 2) atomicAdd(&g_esumsq[2 * l], (double)t);
        else atomicAdd(&g_esumsq[2 * l + 1], (double)t);
    }
}

// ---------------- launch ----------------
extern "C" void kernel_launch(void* const* d_in, const int* in_sizes, int n_in,
                              void* d_out, int out_size) {
    const float* node_inputs = (const float*)d_in[0];
    const float* edge_inputs = (const float*)d_in[1];
    const float* fc_w        = (const float*)d_in[2];
    const float* attn_l      = (const float*)d_in[3];
    const float* attn_r      = (const float*)d_in[4];
    const float* ae_w1       = (const float*)d_in[5];
    const float* ae_b1       = (const float*)d_in[6];
    const float* ae_w2       = (const float*)d_in[7];
    const float* ae_b2       = (const float*)d_in[8];
    const float* bn_n_g      = (const float*)d_in[9];
    const float* bn_n_b      = (const float*)d_in[10];
    const float* eu_node_w   = (const float*)d_in[11];
    const float* eu_edge_w   = (const float*)d_in[12];
    const float* eu_final_w  = (const float*)d_in[13];
    const float* bn_e_g      = (const float*)d_in[14];
    const float* bn_e_b      = (const float*)d_in[15];
    const int*   src         = (const int*)d_in[16];
    const int*   dst         = (const int*)d_in[17];

    float* out_node = (float*)d_out;
    float* out_edge = out_node + (size_t)Nn * HD;

    float* d_ft; cudaGetSymbolAddress((void**)&d_ft, g_ft);
    float* d_pq; cudaGetSymbolAddress((void**)&d_pq, g_pq);
    float* d_wn; cudaGetSymbolAddress((void**)&d_wn, g_wn);

    k_init<<<256, 256>>>();

    dim3 ggrid(HD / BN, (Nn + BM - 1) / BM);
    k_gemm128<<<ggrid, 256>>>(node_inputs, fc_w, d_ft, Nn, HD);

    k_attn<<<(Nn * 32 + 255) / 256, 256>>>(attn_l, attn_r);

    k_hist<<<(Ee + 255) / 256, 256>>>(dst);
    k_scan1<<<(Nn + 511) / 512, 512>>>();
    k_scan2<<<1, 128>>>((Nn + 511) / 512);
    k_scan3<<<128, 256>>>();
    k_scatter<<<(Ee + 255) / 256, 256>>>(dst);

    cudaFuncSetAttribute(k_edge_attn, cudaFuncAttributeMaxDynamicSharedMemorySize,
                         EA_SMEM_FLOATS * 4);
    k_edge_attn<<<Ee / 128, 256, EA_SMEM_FLOATS * 4>>>(
        edge_inputs, ae_w1, ae_b1, ae_w2, ae_b2, src, dst);

    k_agg_fused<<<592, 256>>>(node_inputs, out_node);
    k_bn_prep_node<<<1, 256>>>(bn_n_g, bn_n_b);
    k_node_bn<<<(Nn * HD / 4 + 255) / 256, 256>>>(out_node);

    k_repack<<<128, 256>>>(eu_node_w);
    dim3 pqgrid(1, (Nn + BM - 1) / BM);
    k_gemm128<<<pqgrid, 256>>>(out_node, d_wn, d_pq, Nn, 128);

    cudaFuncSetAttribute(k_edge_update, cudaFuncAttributeMaxDynamicSharedMemorySize,
                         EU_SMEM_FLOATS * 4);
    k_edge_update<<<444, EU_THREADS, EU_SMEM_FLOATS * 4>>>(
        edge_inputs, eu_edge_w, eu_final_w, src, dst, out_edge);

    k_bn_prep_edge<<<1, 64>>>(bn_e_g, bn_e_b);
    k_edge_bn<<<(Ee * EOUT / 4 + 255) / 256, 256>>>(out_edge);
}

// round 5
// speedup vs baseline: 5.5113x; 1.1511x over previous
#include <cuda_runtime.h>
#include <math.h>

#define Nn 50000
#define Ee 400000
#define INDIM 256
#define EDGEF 64
#define OUTD 32
#define EOUT 64
#define Hh 8
#define HD 256           // Hh*OUTD
#define ALPHA 0.2f
#define EPSB 1e-5f

typedef unsigned long long ull;

// ---------------- f32x2 packed-FMA helpers (Blackwell FFMA2) ----------------
__device__ __forceinline__ ull pk(float x, float y) {
    ull r; asm("mov.b64 %0, {%1, %2};" : "=l"(r) : "f"(x), "f"(y)); return r;
}
__device__ __forceinline__ ull pkd(float x) {
    ull r; asm("mov.b64 %0, {%1, %1};" : "=l"(r) : "f"(x)); return r;
}
__device__ __forceinline__ void upk(ull v, float& x, float& y) {
    asm("mov.b64 {%0, %1}, %2;" : "=f"(x), "=f"(y) : "l"(v));
}
__device__ __forceinline__ ull f2fma(ull a, ull b, ull c) {
    ull d; asm("fma.rn.f32x2 %0, %1, %2, %3;" : "=l"(d) : "l"(a), "l"(b), "l"(c));
    return d;
}

// ---------------- scratch (static device globals; no allocation) ----------------
__device__ float g_ft[Nn * HD];          // node projection [N,H,D]
__device__ float g_a1[Nn * Hh];
__device__ float g_a2[Nn * Hh];
__device__ float g_pq[Nn * 128];         // P (cols 0..63) | Q (cols 64..127)
__device__ float g_wn[256 * 128];        // repacked eu_node_w
__device__ float g_apre_s[Ee * Hh];      // dst-sorted attention logits
__device__ int   g_srcs[Ee];             // dst-sorted src index
__device__ int   g_pos[Ee];              // e -> sorted position
__device__ int   g_deg[Nn];
__device__ int   g_cnt[Nn];
__device__ int   g_off[Nn + 1];
__device__ int   g_bsum[128];
__device__ double g_nsum[HD], g_nsumsq[HD];
__device__ double g_esum[EOUT], g_esumsq[EOUT];
__device__ float g_nsc[HD], g_nsh[HD];
__device__ float g_esc[EOUT], g_esh[EOUT];

__device__ __forceinline__ float lrelu(float x) { return x > 0.f ? x : ALPHA * x; }

// ---------------- init: zero counters / stats ----------------
__global__ void k_init() {
    int stride = gridDim.x * blockDim.x;
    for (int i = blockIdx.x * blockDim.x + threadIdx.x; i < Nn; i += stride) {
        g_deg[i] = 0; g_cnt[i] = 0;
        if (i < HD)   { g_nsum[i] = 0.0; g_nsumsq[i] = 0.0; }
        if (i < EOUT) { g_esum[i] = 0.0; g_esumsq[i] = 0.0; }
    }
}

// ---------------- generic GEMM: C[M,N] = A[M,256] @ B[256,N], FFMA2 inner --------
#define BM 128
#define BN 128
#define BK 8
__global__ void __launch_bounds__(256, 2)
k_gemm128(const float* __restrict__ A, const float* __restrict__ B,
          float* __restrict__ C, int M, int N) {
    __shared__ float As[2][BK][BM];
    __shared__ float Bs[2][BK][BN];
    const int K = 256;
    int tid = threadIdx.x;
    int bm = blockIdx.y * BM, bn = blockIdx.x * BN;
    int arow = tid >> 1, acol = (tid & 1) * 4;
    int brow = tid >> 5, bcol = (tid & 31) * 4;
    int tm = (tid >> 4) << 3, tn = (tid & 15) << 3;
    ull acc2[8][4] = {};
    bool aval = (bm + arow) < M;
    float4 a4 = aval ? *(const float4*)&A[(size_t)(bm + arow) * K + acol]
                     : make_float4(0.f, 0.f, 0.f, 0.f);
    float4 b4 = *(const float4*)&B[(size_t)brow * N + bn + bcol];
    As[0][acol + 0][arow] = a4.x; As[0][acol + 1][arow] = a4.y;
    As[0][acol + 2][arow] = a4.z; As[0][acol + 3][arow] = a4.w;
    *(float4*)&Bs[0][brow][bcol] = b4;
    __syncthreads();
    int buf = 0;
    for (int k0 = BK; k0 <= K; k0 += BK) {
        if (k0 < K) {
            a4 = aval ? *(const float4*)&A[(size_t)(bm + arow) * K + k0 + acol]
                      : make_float4(0.f, 0.f, 0.f, 0.f);
            b4 = *(const float4*)&B[(size_t)(k0 + brow) * N + bn + bcol];
        }
        #pragma unroll
        for (int k = 0; k < BK; k++) {
            float ar[8];
            *(float4*)&ar[0] = *(const float4*)&As[buf][k][tm];
            *(float4*)&ar[4] = *(const float4*)&As[buf][k][tm + 4];
            const ull* bp = (const ull*)&Bs[buf][k][tn];
            ull b0 = bp[0], b1 = bp[1], b2 = bp[2], b3 = bp[3];
            #pragma unroll
            for (int i = 0; i < 8; i++) {
                ull aa = pkd(ar[i]);
                acc2[i][0] = f2fma(aa, b0, acc2[i][0]);
                acc2[i][1] = f2fma(aa, b1, acc2[i][1]);
                acc2[i][2] = f2fma(aa, b2, acc2[i][2]);
                acc2[i][3] = f2fma(aa, b3, acc2[i][3]);
            }
        }
        if (k0 < K) {
            int nb = buf ^ 1;
            As[nb][acol + 0][arow] = a4.x; As[nb][acol + 1][arow] = a4.y;
            As[nb][acol + 2][arow] = a4.z; As[nb][acol + 3][arow] = a4.w;
            *(float4*)&Bs[nb][brow][bcol] = b4;
        }
        __syncthreads();
        buf ^= 1;
    }
    #pragma unroll
    for (int i = 0; i < 8; i++) {
        int gm = bm + tm + i;
        if (gm < M) {
            *(ulonglong2*)&C[(size_t)gm * N + bn + tn] =
                make_ulonglong2(acc2[i][0], acc2[i][1]);
            *(ulonglong2*)&C[(size_t)gm * N + bn + tn + 4] =
                make_ulonglong2(acc2[i][2], acc2[i][3]);
        }
    }
}

// repack eu_node_w [512,64] -> g_wn [256,128]
__global__ void k_repack(const float* __restrict__ w) {
    int i = blockIdx.x * blockDim.x + threadIdx.x;
    if (i < 256 * 128) {
        int k = i >> 7, j = i & 127;
        g_wn[i] = (j < 64) ? w[k * 64 + j] : w[(256 + k) * 64 + (j - 64)];
    }
}

// ---------------- per-node, per-head attention scalars (warp/node) --------------
__global__ void k_attn(const float* __restrict__ al, const float* __restrict__ ar) {
    int gw = (blockIdx.x * blockDim.x + threadIdx.x) >> 5;
    int lane = threadIdx.x & 31;
    int h = lane >> 2, p = lane & 3;
    float4 al0 = __ldg((const float4*)&al[h * 32 + p * 4]);
    float4 al1 = __ldg((const float4*)&al[h * 32 + 16 + p * 4]);
    float4 ar0 = __ldg((const float4*)&ar[h * 32 + p * 4]);
    float4 ar1 = __ldg((const float4*)&ar[h * 32 + 16 + p * 4]);
    if (gw >= Nn) return;
    const float4* f = (const float4*)&g_ft[(size_t)gw * HD];
    float4 f0 = f[h * 8 + p], f1 = f[h * 8 + 4 + p];
    float s1 = f0.x * al0.x + f0.y * al0.y + f0.z * al0.z + f0.w * al0.w
             + f1.x * al1.x + f1.y * al1.y + f1.z * al1.z + f1.w * al1.w;
    float s2 = f0.x * ar0.x + f0.y * ar0.y + f0.z * ar0.z + f0.w * ar0.w
             + f1.x * ar1.x + f1.y * ar1.y + f1.z * ar1.z + f1.w * ar1.w;
    s1 += __shfl_xor_sync(0xffffffffu, s1, 1); s1 += __shfl_xor_sync(0xffffffffu, s1, 2);
    s2 += __shfl_xor_sync(0xffffffffu, s2, 1); s2 += __shfl_xor_sync(0xffffffffu, s2, 2);
    if (p == 0) { g_a1[gw * Hh + h] = s1; g_a2[gw * Hh + h] = s2; }
}

// ---------------- counting sort of edges by dst ----------------
__global__ void k_hist(const int* __restrict__ dst) {
    int e = blockIdx.x * blockDim.x + threadIdx.x;
    if (e < Ee) atomicAdd(&g_deg[dst[e]], 1);
}

__global__ void k_scan1() {
    __shared__ int s[512];
    int tid = threadIdx.x;
    int i = blockIdx.x * 512 + tid;
    int v = (i < Nn) ? g_deg[i] : 0;
    s[tid] = v;
    __syncthreads();
    for (int o = 1; o < 512; o <<= 1) {
        int t = (tid >= o) ? s[tid - o] : 0;
        __syncthreads();
        s[tid] += t;
        __syncthreads();
    }
    if (i < Nn) g_off[i] = s[tid] - v;
    if (tid == 511) g_bsum[blockIdx.x] = s[511];
}

__global__ void k_scan2(int nb) {
    __shared__ int s[128];
    int tid = threadIdx.x;
    int v = (tid < nb) ? g_bsum[tid] : 0;
    s[tid] = v;
    __syncthreads();
    for (int o = 1; o < 128; o <<= 1) {
        int t = (tid >= o) ? s[tid - o] : 0;
        __syncthreads();
        s[tid] += t;
        __syncthreads();
    }
    if (tid < nb) g_bsum[tid] = s[tid] - v;
}

__global__ void k_scan3() {
    int stride = gridDim.x * blockDim.x;
    for (int i = blockIdx.x * blockDim.x + threadIdx.x; i < Nn; i += stride)
        g_off[i] += g_bsum[i >> 9];
    if (blockIdx.x == 0 && threadIdx.x == 0) g_off[Nn] = Ee;
}

__global__ void k_scatter(const int* __restrict__ dst) {
    int e = blockIdx.x * blockDim.x + threadIdx.x;
    if (e < Ee) {
        int d = dst[e];
        g_pos[e] = g_off[d] + atomicAdd(&g_cnt[d], 1);
    }
}

// ---------------- edge attention MLP (register-tiled, FFMA2), writes sorted -----
#define EA_SX (64 * 130)
#define EA_SW (64 * 32)
#define EA_SH (128 * 36)
#define EA_SMEM_FLOATS (EA_SX + EA_SW + EA_SH)
__global__ void __launch_bounds__(256)
k_edge_attn(const float* __restrict__ ein,
            const float* __restrict__ w1, const float* __restrict__ b1,
            const float* __restrict__ w2, const float* __restrict__ b2,
            const int* __restrict__ src, const int* __restrict__ dst) {
    extern __shared__ float sm[];
    float* sx  = sm;                 // [k][edge] stride 130
    float* sw1 = sx + EA_SX;         // [k][i] 64x32
    float* sh  = sw1 + EA_SW;        // [edge][hidden] stride 36
    int tid = threadIdx.x;
    int e0 = blockIdx.x * 128;       // Ee % 128 == 0

    for (int i = tid; i < EA_SW; i += 256) sw1[i] = w1[i];
    for (int i = tid; i < 128 * 64; i += 256) {
        int r = i >> 6, c = i & 63;
        sx[c * 130 + r] = ein[(size_t)(e0 + r) * EDGEF + c];
    }
    __syncthreads();

    // layer 1: thread = 2 edges x 8 hidden (FFMA2 over hidden pairs)
    {
        int hg = tid >> 6;           // 0..3
        int ep = tid & 63;           // edge pair
        float4 bb0 = __ldg((const float4*)&b1[hg * 8]);
        float4 bb1 = __ldg((const float4*)&b1[hg * 8 + 4]);
        ull A0[4], A1[4];
        A0[0] = pk(bb0.x, bb0.y); A0[1] = pk(bb0.z, bb0.w);
        A0[2] = pk(bb1.x, bb1.y); A0[3] = pk(bb1.z, bb1.w);
        #pragma unroll
        for (int j = 0; j < 4; j++) A1[j] = A0[j];
        #pragma unroll 4
        for (int k = 0; k < 64; k++) {
            float2 a = *(const float2*)&sx[k * 130 + 2 * ep];
            const ulonglong2* wp = (const ulonglong2*)&sw1[k * 32 + hg * 8];
            ulonglong2 wA = wp[0], wB = wp[1];
            ull ax = pkd(a.x), ay = pkd(a.y);
            A0[0] = f2fma(ax, wA.x, A0[0]); A0[1] = f2fma(ax, wA.y, A0[1]);
            A0[2] = f2fma(ax, wB.x, A0[2]); A0[3] = f2fma(ax, wB.y, A0[3]);
            A1[0] = f2fma(ay, wA.x, A1[0]); A1[1] = f2fma(ay, wA.y, A1[1]);
            A1[2] = f2fma(ay, wB.x, A1[2]); A1[3] = f2fma(ay, wB.y, A1[3]);
        }
        float* h0 = &sh[(2 * ep) * 36 + hg * 8];
        float* h1 = &sh[(2 * ep + 1) * 36 + hg * 8];
        #pragma unroll
        for (int j = 0; j < 4; j++) {
            float x, y;
            upk(A0[j], x, y); h0[2 * j] = lrelu(x); h0[2 * j + 1] = lrelu(y);
            upk(A1[j], x, y); h1[2 * j] = lrelu(x); h1[2 * j + 1] = lrelu(y);
        }
    }
    __syncthreads();

    // layer 2 + epilogue: thread = 1 edge-half (4 heads)
    {
        int el = tid >> 1, half = tid & 1, hs = half * 4;
        int e = e0 + el;
        float4 bb = __ldg((const float4*)&b2[hs]);
        ull ac0 = pk(bb.x, bb.y), ac1 = pk(bb.z, bb.w);
        const float* hrow = &sh[el * 36];
        #pragma unroll 8
        for (int i = 0; i < 32; i++) {
            ull sp = pkd(hrow[i]);
            ulonglong2 wq = *(const ulonglong2*)&w2[i * 8 + hs];
            ac0 = f2fma(sp, wq.x, ac0);
            ac1 = f2fma(sp, wq.y, ac1);
        }
        float acc[4];
        upk(ac0, acc[0], acc[1]); upk(ac1, acc[2], acc[3]);
        int sn = src[e], dn = dst[e];
        int pos = g_pos[e];
        if (half == 0) g_srcs[pos] = sn;
        float4 A1v = *(const float4*)&g_a1[sn * 8 + hs];
        float4 A2v = *(const float4*)&g_a2[dn * 8 + hs];
        float4 o;
        o.x = lrelu(acc[0] + A1v.x + A2v.x);
        o.y = lrelu(acc[1] + A1v.y + A2v.y);
        o.z = lrelu(acc[2] + A1v.z + A2v.z);
        o.w = lrelu(acc[3] + A1v.w + A2v.w);
        *(float4*)&g_apre_s[(size_t)pos * 8 + hs] = o;
    }
}

// ---------------- fused: softmax + aggregate + residual + lrelu + BN stats -------
__global__ void __launch_bounds__(256)
k_agg_fused(const float* __restrict__ nin, float* __restrict__ ynode) {
    int lane = threadIdx.x & 31;
    int wid = (blockIdx.x * blockDim.x + threadIdx.x) >> 5;
    int nw = (gridDim.x * blockDim.x) >> 5;
    int sub = lane >> 3, h = lane & 7;
    float s[8] = {}, s2[8] = {};
    for (int n = wid; n < Nn; n += nw) {
        int start = g_off[n], end = g_off[n + 1];
        int deg = end - start;
        float acc[8] = {};
        float zz = 0.f;
        if (deg > 0) {
            float am = -INFINITY;
            for (int i = sub; i < deg; i += 4)
                am = fmaxf(am, g_apre_s[(size_t)(start + i) * 8 + h]);
            am = fmaxf(am, __shfl_xor_sync(0xffffffffu, am, 8));
            am = fmaxf(am, __shfl_xor_sync(0xffffffffu, am, 16));
            for (int i = 0; i < deg; i += 4) {
                float w = 0.f;
                if (i + sub < deg)
                    w = __expf(g_apre_s[(size_t)(start + i + sub) * 8 + h] - am);
                zz += w;
                int sn4 = 0;
                if (lane < 4 && i + lane < deg) sn4 = g_srcs[start + i + lane];
                #pragma unroll
                for (int e = 0; e < 4; e++) {
                    int sn = __shfl_sync(0xffffffffu, sn4, e);
                    const float* ftr = &g_ft[(size_t)sn * HD + lane];
                    #pragma unroll
                    for (int j = 0; j < 8; j++) {
                        float wj = __shfl_sync(0xffffffffu, w, e * 8 + j);
                        acc[j] += wj * ftr[j * 32];
                    }
                }
            }
            zz += __shfl_xor_sync(0xffffffffu, zz, 8);
            zz += __shfl_xor_sync(0xffffffffu, zz, 16);
        }
        #pragma unroll
        for (int j = 0; j < 8; j++) {
            float zj = __shfl_sync(0xffffffffu, zz, j);
            if (zj == 0.f) zj = 1.f;
            float v = acc[j] / zj + nin[(size_t)n * HD + j * 32 + lane];
            v = lrelu(v);
            ynode[(size_t)n * HD + j * 32 + lane] = v;
            s[j] += v; s2[j] += v * v;
        }
    }
    __shared__ float red[8][512];
    int w = threadIdx.x >> 5;
    #pragma unroll
    for (int j = 0; j < 8; j++) {
        red[w][j * 32 + lane] = s[j];
        red[w][256 + j * 32 + lane] = s2[j];
    }
    __syncthreads();
    if (threadIdx.x < 256) {
        float ts = 0.f, ts2 = 0.f;
        #pragma unroll
        for (int ww = 0; ww < 8; ww++) { ts += red[ww][threadIdx.x]; ts2 += red[ww][256 + threadIdx.x]; }
        atomicAdd(&g_nsum[threadIdx.x], (double)ts);
        atomicAdd(&g_nsumsq[threadIdx.x], (double)ts2);
    }
}

// ---------------- BN prep (fp64 once per column) ----------------
__global__ void k_bn_prep_node(const float* __restrict__ g, const float* __restrict__ b) {
    int c = threadIdx.x;
    double mu = g_nsum[c] / (double)Nn;
    double var = g_nsumsq[c] / (double)Nn - mu * mu;
    float sc = rsqrtf((float)var + EPSB) * g[c];
    g_nsc[c] = sc;
    g_nsh[c] = b[c] - (float)mu * sc;
}
__global__ void k_bn_prep_edge(const float* __restrict__ g, const float* __restrict__ b) {
    int c = threadIdx.x;
    double mu = g_esum[c] / (double)Ee;
    double var = g_esumsq[c] / (double)Ee - mu * mu;
    float sc = rsqrtf((float)var + EPSB) * g[c];
    g_esc[c] = sc;
    g_esh[c] = b[c] - (float)mu * sc;
}

__global__ void k_node_bn(float* __restrict__ ynode) {
    int i = blockIdx.x * blockDim.x + threadIdx.x;   // float4 index
    if (i < Nn * HD / 4) {
        int cb = (i & 63) * 4;
        float4 v = ((float4*)ynode)[i];
        float4 sc = *(const float4*)&g_nsc[cb];
        float4 sh = *(const float4*)&g_nsh[cb];
        v.x = v.x * sc.x + sh.x; v.y = v.y * sc.y + sh.y;
        v.z = v.z * sc.z + sh.z; v.w = v.w * sc.w + sh.w;
        ((float4*)ynode)[i] = v;
    }
}

__global__ void k_edge_bn(float* __restrict__ yedge) {
    int i = blockIdx.x * blockDim.x + threadIdx.x;
    if (i < Ee * EOUT / 4) {
        int cb = (i & 15) * 4;
        float4 v = ((float4*)yedge)[i];
        float4 sc = *(const float4*)&g_esc[cb];
        float4 sh = *(const float4*)&g_esh[cb];
        v.x = v.x * sc.x + sh.x; v.y = v.y * sc.y + sh.y;
        v.z = v.z * sc.z + sh.z; v.w = v.w * sc.w + sh.w;
        ((float4*)yedge)[i] = v;
    }
}

// ---------------- edge update MLP: 8 edges/warp, FFMA2 ----------------
#define EU_THREADS 256
#define EU_WARPS 8
#define EU_B 8
// smem floats: W2 4096 + W3 8192 + per-warp stage (se 512 + xw 1024) * 8
#define EU_STAGE (EU_WARPS * 1536)
#define EU_SMEM_FLOATS (4096 + 8192 + EU_STAGE)
__global__ void __launch_bounds__(EU_THREADS, 2)
k_edge_update(const float* __restrict__ ein,
              const float* __restrict__ W2g, const float* __restrict__ W3g,
              const int* __restrict__ src, const int* __restrict__ dst,
              float* __restrict__ yedge) {
    extern __shared__ float sm[];
    float* W2 = sm;                  // [k][out] 64x64
    float* W3 = W2 + 4096;           // [k][out] 128x64
    float* stage = W3 + 8192;
    int tid = threadIdx.x;
    for (int i = tid; i < 4096; i += EU_THREADS) W2[i] = W2g[i];
    for (int i = tid; i < 8192; i += EU_THREADS) W3[i] = W3g[i];
    __syncthreads();
    int wid = tid >> 5, lane = tid & 31;
    float* se = stage + wid * 1536;  // 8 x 64
    float* xw = se + 512;            // 8 x 128
    int nwarps = gridDim.x * EU_WARPS;
    int gw0 = blockIdx.x * EU_WARPS + wid;
    const int NG = Ee / EU_B;        // 50000 groups

    float s0 = 0.f, s1 = 0.f, q0 = 0.f, q1 = 0.f;

    for (int g = gw0; g < NG; g += nwarps) {
        int base = g * EU_B;
        float2 er[EU_B];
        #pragma unroll
        for (int e = 0; e < EU_B; e++) {
            int sn = src[base + e], dn = dst[base + e];
            er[e] = *(const float2*)&ein[(size_t)(base + e) * EDGEF + 2 * lane];
            float2 p = *(const float2*)&g_pq[(size_t)sn * 128 + 2 * lane];
            float2 q = *(const float2*)&g_pq[(size_t)dn * 128 + 64 + 2 * lane];
            float2 nf2; nf2.x = lrelu(p.x + q.x); nf2.y = lrelu(p.y + q.y);
            *(float2*)&se[e * 64 + 2 * lane] = er[e];
            *(float2*)&xw[e * 128 + 2 * lane] = nf2;
        }
        __syncwarp();

        // ef = lrelu(ein @ W2)
        ull ef2[EU_B] = {};
        #pragma unroll
        for (int k0 = 0; k0 < 64; k0 += 4) {
            float xs[EU_B][4];
            #pragma unroll
            for (int e = 0; e < EU_B; e++)
                *(float4*)xs[e] = *(const float4*)&se[e * 64 + k0];
            #pragma unroll
            for (int j = 0; j < 4; j++) {
                ull w = *(const ull*)&W2[(k0 + j) * 64 + 2 * lane];
                #pragma unroll
                for (int e = 0; e < EU_B; e++)
                    ef2[e] = f2fma(pkd(xs[e][j]), w, ef2[e]);
            }
        }
        #pragma unroll
        for (int e = 0; e < EU_B; e++) {
            float x, y; upk(ef2[e], x, y);
            float2 v; v.x = lrelu(x); v.y = lrelu(y);
            *(float2*)&xw[e * 128 + 64 + 2 * lane] = v;
        }
        __syncwarp();

        // o = concat(nf, ef) @ W3 + ein residual
        ull o2[EU_B];
        #pragma unroll
        for (int e = 0; e < EU_B; e++) o2[e] = pk(er[e].x, er[e].y);
        #pragma unroll
        for (int k0 = 0; k0 < 128; k0 += 4) {
            float xs[EU_B][4];
            #pragma unroll
            for (int e = 0; e < EU_B; e++)
                *(float4*)xs[e] = *(const float4*)&xw[e * 128 + k0];
            #pragma unroll
            for (int j = 0; j < 4; j++) {
                ull w = *(const ull*)&W3[(k0 + j) * 64 + 2 * lane];
                #pragma unroll
                for (int e = 0; e < EU_B; e++)
                    o2[e] = f2fma(pkd(xs[e][j]), w, o2[e]);
            }
        }
        #pragma unroll
        for (int e = 0; e < EU_B; e++) {
            float x, y; upk(o2[e], x, y);
            float a = lrelu(x), b = lrelu(y);
            float2 outv; outv.x = a; outv.y = b;
            *(float2*)&yedge[(size_t)(base + e) * EOUT + 2 * lane] = outv;
            s0 += a; s1 += b; q0 += a * a; q1 += b * b;
        }
        __syncwarp();
    }

    // block-level reduction of BN partials
    __syncthreads();
    float* red = stage;
    red[wid * 512 + lane * 4 + 0] = s0;
    red[wid * 512 + lane * 4 + 1] = s1;
    red[wid * 512 + lane * 4 + 2] = q0;
    red[wid * 512 + lane * 4 + 3] = q1;
    __syncthreads();
    if (tid < 128) {
        float t = 0.f;
        #pragma unroll
        for (int w = 0; w < EU_WARPS; w++) t += red[w * 512 + tid];
        int l = tid >> 2, part = tid & 3;
        if (part == 0) atomicAdd(&g_esum[2 * l], (double)t);
        else if (part == 1) atomicAdd(&g_esum[2 * l + 1], (double)t);
        else if (part == 2) atomicAdd(&g_esumsq[2 * l], (double)t);
        else atomicAdd(&g_esumsq[2 * l + 1], (double)t);
    }
}

// ---------------- launch ----------------
extern "C" void kernel_launch(void* const* d_in, const int* in_sizes, int n_in,
                              void* d_out, int out_size) {
    const float* node_inputs = (const float*)d_in[0];
    const float* edge_inputs = (const float*)d_in[1];
    const float* fc_w        = (const float*)d_in[2];
    const float* attn_l      = (const float*)d_in[3];
    const float* attn_r      = (const float*)d_in[4];
    const float* ae_w1       = (const float*)d_in[5];
    const float* ae_b1       = (const float*)d_in[6];
    const float* ae_w2       = (const float*)d_in[7];
    const float* ae_b2       = (const float*)d_in[8];
    const float* bn_n_g      = (const float*)d_in[9];
    const float* bn_n_b      = (const float*)d_in[10];
    const float* eu_node_w   = (const float*)d_in[11];
    const float* eu_edge_w   = (const float*)d_in[12];
    const float* eu_final_w  = (const float*)d_in[13];
    const float* bn_e_g      = (const float*)d_in[14];
    const float* bn_e_b      = (const float*)d_in[15];
    const int*   src         = (const int*)d_in[16];
    const int*   dst         = (const int*)d_in[17];

    float* out_node = (float*)d_out;
    float* out_edge = out_node + (size_t)Nn * HD;

    float* d_ft; cudaGetSymbolAddress((void**)&d_ft, g_ft);
    float* d_pq; cudaGetSymbolAddress((void**)&d_pq, g_pq);
    float* d_wn; cudaGetSymbolAddress((void**)&d_wn, g_wn);

    k_init<<<256, 256>>>();

    dim3 ggrid(HD / BN, (Nn + BM - 1) / BM);
    k_gemm128<<<ggrid, 256>>>(node_inputs, fc_w, d_ft, Nn, HD);

    k_attn<<<(Nn * 32 + 255) / 256, 256>>>(attn_l, attn_r);

    k_hist<<<(Ee + 255) / 256, 256>>>(dst);
    k_scan1<<<(Nn + 511) / 512, 512>>>();
    k_scan2<<<1, 128>>>((Nn + 511) / 512);
    k_scan3<<<128, 256>>>();
    k_scatter<<<(Ee + 255) / 256, 256>>>(dst);

    cudaFuncSetAttribute(k_edge_attn, cudaFuncAttributeMaxDynamicSharedMemorySize,
                         EA_SMEM_FLOATS * 4);
    k_edge_attn<<<Ee / 128, 256, EA_SMEM_FLOATS * 4>>>(
        edge_inputs, ae_w1, ae_b1, ae_w2, ae_b2, src, dst);

    k_agg_fused<<<592, 256>>>(node_inputs, out_node);
    k_bn_prep_node<<<1, 256>>>(bn_n_g, bn_n_b);
    k_node_bn<<<(Nn * HD / 4 + 255) / 256, 256>>>(out_node);

    k_repack<<<128, 256>>>(eu_node_w);
    dim3 pqgrid(1, (Nn + BM - 1) / BM);
    k_gemm128<<<pqgrid, 256>>>(out_node, d_wn, d_pq, Nn, 128);

    cudaFuncSetAttribute(k_edge_update, cudaFuncAttributeMaxDynamicSharedMemorySize,
                         EU_SMEM_FLOATS * 4);
    k_edge_update<<<296, EU_THREADS, EU_SMEM_FLOATS * 4>>>(
        edge_inputs, eu_edge_w, eu_final_w, src, dst, out_edge);

    k_bn_prep_edge<<<1, 64>>>(bn_e_g, bn_e_b);
    k_edge_bn<<<(Ee * EOUT / 4 + 255) / 256, 256>>>(out_edge);
}